// round 10
// baseline (speedup 1.0000x reference)
#include <cuda_runtime.h>
#include <cuda_bf16.h>
#include <math.h>

#define BATCH 32
#define NNODE 33
#define NSTR  40
#define NPAD  36
#define CH    64

typedef unsigned long long u64;
typedef unsigned int u32;
typedef unsigned short u16;

// ---------------- f32x2 helpers ----------------
__device__ __forceinline__ u64 pk2(float lo, float hi) {
    u64 r;
    asm("mov.b64 %0, {%1, %2};" : "=l"(r) : "r"(__float_as_uint(lo)), "r"(__float_as_uint(hi)));
    return r;
}
__device__ __forceinline__ u64 dup2(float v) { return pk2(v, v); }
__device__ __forceinline__ void unpk2(u64 v, float& lo, float& hi) {
    u32 a, b;
    asm("mov.b64 {%0, %1}, %2;" : "=r"(a), "=r"(b) : "l"(v));
    lo = __uint_as_float(a);
    hi = __uint_as_float(b);
}
__device__ __forceinline__ void fma2(u64& d, u64 a, u64 b) {
    asm("fma.rn.f32x2 %0, %1, %2, %0;" : "+l"(d) : "l"(a), "l"(b));
}

// ---------------- mma.sync / ldmatrix helpers ----------------
__device__ __forceinline__ u32 smem_u32(const void* p) {
    u32 a;
    asm("{ .reg .u64 t; cvta.to.shared.u64 t, %1; cvt.u32.u64 %0, t; }" : "=r"(a) : "l"(p));
    return a;
}
__device__ __forceinline__ void ldsm_x4(u32* r, u32 addr) {
    asm volatile("ldmatrix.sync.aligned.m8n8.x4.shared.b16 {%0,%1,%2,%3}, [%4];"
                 : "=r"(r[0]), "=r"(r[1]), "=r"(r[2]), "=r"(r[3]) : "r"(addr));
}
__device__ __forceinline__ void mma_bf16(float* c, const u32* a, u32 b0, u32 b1) {
    asm volatile("mma.sync.aligned.m16n8k16.row.col.f32.bf16.bf16.f32 "
                 "{%0,%1,%2,%3}, {%4,%5,%6,%7}, {%8,%9}, {%0,%1,%2,%3};"
                 : "+f"(c[0]), "+f"(c[1]), "+f"(c[2]), "+f"(c[3])
                 : "r"(a[0]), "r"(a[1]), "r"(a[2]), "r"(a[3]), "r"(b0), "r"(b1));
}
__device__ __forceinline__ u64 pack4bf(__nv_bfloat16 a, __nv_bfloat16 b,
                                       __nv_bfloat16 c, __nv_bfloat16 d) {
    u32 u0 = ((u32)__bfloat16_as_ushort(b) << 16) | (u32)__bfloat16_as_ushort(a);
    u32 u1 = ((u32)__bfloat16_as_ushort(d) << 16) | (u32)__bfloat16_as_ushort(c);
    return (u64)u0 | ((u64)u1 << 32);
}
__device__ __forceinline__ void bfsplit(float v, u16& h, u16& l) {
    __nv_bfloat16 hb = __float2bfloat16(v);
    h = __bfloat16_as_ushort(hb);
    l = __bfloat16_as_ushort(__float2bfloat16(v - __bfloat162float(hb)));
}

// ---------------- device scratch ----------------
#define BUF_ELEMS ((size_t)BATCH * 510 * NSTR * CH)
__device__ float g_bufA[BUF_ELEMS];
__device__ float g_bufB[BUF_ELEMS];
__device__ float g_L[NPAD * NPAD];
__device__ float g_L2[NPAD * NPAD];
__device__ float g_w1a[3 * 3 * 3 * 64];
__device__ u32   g_Bw1[36864], g_Bw2[36864], g_Bw3[36864];
__device__ u32   g_Cw1[12288], g_Cw2[12288];
__device__ float g_scl1[NNODE], g_shf1[NNODE];
__device__ float g_scl2[NNODE], g_shf2[NNODE];
__device__ double g_sum1[NNODE], g_sqs1[NNODE];
__device__ double g_sum2[NNODE], g_sqs2[NNODE];
__device__ float g_M[BATCH * NNODE * CH];

// ---------------- setup ----------------
__global__ void setup_kernel(const int* __restrict__ ei, int ne, const float* __restrict__ w3) {
    __shared__ float sL[NPAD * NPAD];
    int i = threadIdx.x;
    if (i < NNODE) { g_sum1[i] = 0.0; g_sqs1[i] = 0.0; g_sum2[i] = 0.0; g_sqs2[i] = 0.0; }
    for (int j = i; j < 3 * 3 * 3 * 64; j += 64) {
        int o  = j & 63;
        int k  = (j >> 6) % 3;
        int ci = (j / 192) % 3;
        int g  = j / (192 * 3);
        g_w1a[j] = w3[((g * 64 + o) * 3 + ci) * 3 + k];
    }
    if (i == 0) {
        double deg[NNODE];
        for (int k = 0; k < NNODE; k++) deg[k] = 0.0;
        for (int e = 0; e < ne; e++) deg[ei[e]] += 1.0;
        double dinv[NNODE];
        for (int k = 0; k < NNODE; k++) dinv[k] = (deg[k] > 0.0) ? (1.0 / sqrt(deg[k])) : 0.0;
        for (int k = 0; k < NPAD * NPAD; k++) sL[k] = 0.0f;
        for (int e = 0; e < ne; e++) {
            int s = ei[e];
            int t = ei[ne + e];
            sL[t * NPAD + s] += (float)(-dinv[s] * dinv[t]);
        }
        for (int k = 0; k < NPAD * NPAD; k++) g_L[k] = sL[k];
    }
    __syncthreads();
    for (int idx = i; idx < NPAD * NPAD; idx += 64) {
        int r = idx / NPAD, c = idx % NPAD;
        float s = 0.f;
        for (int m = 0; m < NPAD; m++) s = fmaf(sL[r * NPAD + m], sL[m * NPAD + c], s);
        g_L2[idx] = s;
    }
}

// ---- tconv weights -> bf16 hi/lo regions ----
__global__ void convert_w_kernel(const float* __restrict__ w, u32* __restrict__ outw) {
    int i = blockIdx.x * blockDim.x + threadIdx.x;
    if (i >= 36864) return;
    int region = i >> 11;
    int rem    = i & 2047;
    int o      = rem >> 5;
    int c2     = rem & 31;
    int s  = region & 1;
    int gk = region >> 1;
    int g  = gk / 3, k = gk % 3;
    int ci0 = 2 * c2;
    float v0 = w[((g * 64 + o) * 64 + ci0) * 3 + k];
    float v1 = w[((g * 64 + o) * 64 + ci0 + 1) * 3 + k];
    u16 h0, l0, h1, l1;
    bfsplit(v0, h0, l0);
    bfsplit(v1, h1, l1);
    outw[i] = (s == 0) ? (((u32)h1 << 16) | (u32)h0) : (((u32)l1 << 16) | (u32)l0);
}

// ---- cheb weights -> flat Veff [s][dg=k*64+d][c-pair], Veff = [W0-W2, W1, 2*W2] ----
__device__ __forceinline__ float veff(const float* cw, int k, int c, int d) {
    if (k == 0) return cw[(0 * 64 + c) * 64 + d] - cw[(2 * 64 + c) * 64 + d];
    if (k == 1) return cw[(1 * 64 + c) * 64 + d];
    return 2.f * cw[(2 * 64 + c) * 64 + d];
}
__global__ void convert_cw_kernel(const float* __restrict__ cw1, u32* __restrict__ o1,
                                  const float* __restrict__ cw2, u32* __restrict__ o2) {
    int i = blockIdx.x * blockDim.x + threadIdx.x;
    if (i >= 24576) return;
    const float* cw = (i < 12288) ? cw1 : cw2;
    u32* op = (i < 12288) ? o1 : o2;
    int j = (i < 12288) ? i : (i - 12288);
    int s   = j / 6144;
    int rem = j - s * 6144;
    int dg  = rem >> 5, c2 = rem & 31;
    int k = dg >> 6, d = dg & 63, c0 = 2 * c2;
    float v0 = veff(cw, k, c0, d);
    float v1 = veff(cw, k, c0 + 1, d);
    u16 h0, l0, h1, l1;
    bfsplit(v0, h0, l0);
    bfsplit(v1, h1, l1);
    op[j] = (s == 0) ? (((u32)h1 << 16) | (u32)h0) : (((u32)l1 << 16) | (u32)l0);
}

// ---------------- SIMT gated tconv CI=3 (first layer) ----------------
__global__ void __launch_bounds__(512)
tconv3_kernel(const float* __restrict__ xin,
              const float* __restrict__ bias,
              float* __restrict__ out) {
    constexpr int CI = 3, CT = 128, TO = 16, ST = CT + 4, HP = TO / 2;
    constexpr int Tin = 512, Tout = 510;
    __shared__ float ws[3 * CI * 3 * 64];
    __shared__ float xs[CI * ST];

    const int tid = threadIdx.y * 64 + threadIdx.x;
    const int ntch = (Tout + CT - 1) / CT;
    const int ntiles = ntch * NNODE * BATCH;

    for (int i = tid; i < 3 * CI * 3 * 64; i += 512) ws[i] = g_w1a[i];

    const int o  = threadIdx.x;
    const int tb = threadIdx.y * TO;
    const float bP = bias[o], bQ = bias[64 + o], bR = bias[128 + o];

    for (int tile = blockIdx.x; tile < ntiles; tile += gridDim.x) {
        const int tch = tile % ntch;
        const int rem = tile / ntch;
        const int n   = rem % NNODE;
        const int b   = rem / NNODE;
        const int t0  = tch * CT;

        __syncthreads();
        for (int i = tid; i < (CT + 2) * CI; i += 512) {
            int tt = i / CI, ci = i % CI;
            int t = t0 + tt;
            float v = 0.f;
            if (t < Tin) v = xin[(((size_t)b * Tin + t) * NNODE + n) * CI + ci];
            xs[ci * ST + tt] = v;
        }
        __syncthreads();

        u64 accP[3][HP];
#pragma unroll
        for (int g = 0; g < 3; g++)
#pragma unroll
            for (int p = 0; p < HP; p++) accP[g][p] = 0ull;

#pragma unroll
        for (int ci = 0; ci < CI; ci++) {
            const float* xp = &xs[ci * ST + tb];
            u64 ep[HP + 1];
#pragma unroll
            for (int p = 0; p <= HP; p++) ep[p] = *reinterpret_cast<const u64*>(xp + 2 * p);
            float xl[HP + 1], xh[HP + 1];
#pragma unroll
            for (int p = 0; p <= HP; p++) unpk2(ep[p], xl[p], xh[p]);
            u64 op[HP];
#pragma unroll
            for (int p = 0; p < HP; p++) op[p] = pk2(xh[p], xl[p + 1]);

#pragma unroll
            for (int g = 0; g < 3; g++) {
#pragma unroll
                for (int k = 0; k < 3; k++) {
                    u64 wd = dup2(ws[((g * CI + ci) * 3 + k) * 64 + o]);
                    const u64* xq = (k == 0) ? ep : (k == 1) ? op : (ep + 1);
#pragma unroll
                    for (int p = 0; p < HP; p++) fma2(accP[g][p], xq[p], wd);
                }
            }
        }

#pragma unroll
        for (int p = 0; p < HP; p++) {
            float P0, P1, Q0, Q1, R0, R1;
            unpk2(accP[0][p], P0, P1);
            unpk2(accP[1][p], Q0, Q1);
            unpk2(accP[2][p], R0, R1);
#pragma unroll
            for (int half = 0; half < 2; half++) {
                int t = t0 + tb + 2 * p + half;
                if (t < Tout) {
                    float P = (half ? P1 : P0) + bP;
                    float Q = (half ? Q1 : Q0) + bQ;
                    float R = (half ? R1 : R0) + bR;
                    float sg = 1.f / (1.f + __expf(-Q));
                    float h = fmaxf(fmaf(P, sg, R), 0.f);
                    out[(((size_t)b * Tout + t) * NSTR + n) * CH + o] = h;
                }
            }
        }
    }
}

// ---------------- mma.sync gated tconv CI=64 (512 threads, 16 warps) ----------------
#define ROWS_A 208
#define A_SPLIT_B (ROWS_A * 128)
#define B_BYTES   (18 * 8192)
#define OFF_B     1024
#define OFF_A     (OFF_B + B_BYTES)
#define TC_SMEM   (OFF_A + 2 * A_SPLIT_B + 1024)

__global__ void __launch_bounds__(512, 1)
tconv_mma_kernel(const float* __restrict__ xin, int Tin,
                 const u32* __restrict__ Bw,
                 const float* __restrict__ bias,
                 const float* __restrict__ scl, const float* __restrict__ shf, int mode,
                 float* __restrict__ out) {
    extern __shared__ char smraw[];
    __shared__ float sbias[192];

    const u32 sb0 = smem_u32(smraw);
    const u32 sbase = (sb0 + 1023) & ~1023u;
    char* sm = smraw + (sbase - sb0);

    const int tid = threadIdx.x;
    const int wid = tid >> 5, lane = tid & 31;
    const int Tout = Tin - 2;
    const int RowsIn = Tin * NSTR, RowsOut = Tout * NSTR;
    const int ntb = (RowsOut + 127) / 128;
    const int ntiles = ntb * BATCH;

    for (int i = tid; i < 36864; i += 512) {
        int r = i >> 11, rem = i & 2047, row = rem >> 5, c2 = rem & 31;
        u32 byte = row * 128 + c2 * 4;
        *(u32*)(sm + OFF_B + r * 8192 + (byte ^ ((byte >> 3) & 0x70))) = Bw[i];
    }
    if (tid < 192) sbias[tid] = bias[tid];
    __syncthreads();

    const int warp_m = wid & 7;
    const int o0 = (wid >> 3) * 32;

    const u32 a_row_l = lane & 15;
    const u32 a_koff  = (lane & 16) ? 16u : 0u;
    const u32 b_row_l = lane & 7;
    const u32 b_koff  = (lane & 8) ? 16u : 0u;
    const u32 b_sreg  = (lane & 16) ? 8192u : 0u;

    const int trow = lane >> 2;
    const int tcol = (lane & 3) * 2;

    for (int tile = blockIdx.x; tile < ntiles; tile += gridDim.x) {
        const int bidx = tile / ntb, tl = tile % ntb;
        const int local0 = tl * 128;
        const float* xb = xin + (size_t)bidx * RowsIn * 64;

        __syncthreads();

        for (int i4 = tid; i4 < ROWS_A * 16; i4 += 512) {
            int r = i4 >> 4, c4 = (i4 & 15) << 2;
            int il = local0 + r;
            float4 v = make_float4(0.f, 0.f, 0.f, 0.f);
            if (il < RowsIn) {
                int n = il % NSTR;
                if (n < NNODE) {
                    v = *(const float4*)(xb + (size_t)il * 64 + c4);
                    if (mode) {
                        float sc = scl[n], sh = shf[n];
                        v.x = fmaxf(fmaf(v.x, sc, sh), 0.f);
                        v.y = fmaxf(fmaf(v.y, sc, sh), 0.f);
                        v.z = fmaxf(fmaf(v.z, sc, sh), 0.f);
                        v.w = fmaxf(fmaf(v.w, sc, sh), 0.f);
                    }
                }
            }
            __nv_bfloat16 hx = __float2bfloat16(v.x), hy = __float2bfloat16(v.y);
            __nv_bfloat16 hz = __float2bfloat16(v.z), hw = __float2bfloat16(v.w);
            u32 byte = r * 128 + (c4 << 1);
            u32 sw = byte ^ ((byte >> 3) & 0x70);
            *(u64*)(sm + OFF_A + sw) = pack4bf(hx, hy, hz, hw);
            __nv_bfloat16 lx = __float2bfloat16(v.x - __bfloat162float(hx));
            __nv_bfloat16 ly = __float2bfloat16(v.y - __bfloat162float(hy));
            __nv_bfloat16 lz = __float2bfloat16(v.z - __bfloat162float(hz));
            __nv_bfloat16 lw = __float2bfloat16(v.w - __bfloat162float(hw));
            *(u64*)(sm + OFF_A + A_SPLIT_B + sw) = pack4bf(lx, ly, lz, lw);
        }
        __syncthreads();

        float acc[3][4][4];
#pragma unroll
        for (int g = 0; g < 3; g++)
#pragma unroll
            for (int ot = 0; ot < 4; ot++)
#pragma unroll
                for (int c = 0; c < 4; c++) acc[g][ot][c] = 0.f;

#pragma unroll
        for (int tap = 0; tap < 3; tap++) {
#pragma unroll
            for (int kc = 0; kc < 4; kc++) {
                u32 ah[4], al[4];
                {
                    u32 rb = (u32)(tap * 40 + warp_m * 16) + a_row_l;
                    u32 byte = rb * 128 + (u32)(kc * 32) + a_koff;
                    u32 sw = byte ^ ((byte >> 3) & 0x70);
                    ldsm_x4(ah, sbase + OFF_A + sw);
                    ldsm_x4(al, sbase + OFF_A + A_SPLIT_B + sw);
                }
#pragma unroll
                for (int g = 0; g < 3; g++) {
                    u32 breg = sbase + OFF_B + (u32)((g * 3 + tap) * 2) * 8192 + b_sreg;
                    u32 bf[4][4];
#pragma unroll
                    for (int ot = 0; ot < 4; ot++) {
                        u32 byte = (u32)(o0 + 8 * ot + (int)b_row_l) * 128 + (u32)(kc * 32) + b_koff;
                        ldsm_x4(bf[ot], breg + (byte ^ ((byte >> 3) & 0x70)));
                    }
#pragma unroll
                    for (int ot = 0; ot < 4; ot++)
                        mma_bf16(acc[g][ot], ah, bf[ot][0], bf[ot][1]);
#pragma unroll
                    for (int ot = 0; ot < 4; ot++)
                        mma_bf16(acc[g][ot], al, bf[ot][0], bf[ot][1]);
#pragma unroll
                    for (int ot = 0; ot < 4; ot++)
                        mma_bf16(acc[g][ot], ah, bf[ot][2], bf[ot][3]);
                }
            }
        }

#pragma unroll
        for (int rs = 0; rs < 2; rs++) {
            int row = warp_m * 16 + trow + rs * 8;
            int ol = local0 + row;
            if (ol < RowsOut) {
                float* op = out + ((size_t)bidx * RowsOut + ol) * 64;
#pragma unroll
                for (int ot = 0; ot < 4; ot++) {
                    int o = o0 + 8 * ot + tcol;
                    float2 hv;
#pragma unroll
                    for (int e = 0; e < 2; e++) {
                        float P = acc[0][ot][rs * 2 + e] + sbias[o + e];
                        float Q = acc[1][ot][rs * 2 + e] + sbias[64 + o + e];
                        float R = acc[2][ot][rs * 2 + e] + sbias[128 + o + e];
                        float sg = 1.f / (1.f + __expf(-Q));
                        float hval = fmaxf(fmaf(P, sg, R), 0.f);
                        if (e == 0) hv.x = hval; else hv.y = hval;
                    }
                    *(float2*)(op + o) = hv;
                }
            }
        }
    }
}

// ---------------- cheb v3: GEMM-first (Y = Z*Veff, N=192) + fp32 L-mixing epilogue ----------------
#define CH_OFF_W  0                     // Veff hi 24576 | lo 24576
#define CH_OFF_A  49152                 // Z hi 16384 | lo 16384
#define CH_OFF_Y  81920                 // Y: 120 x 196 f32
#define CH_YSTR   196
#define CH_DYN    (81920 + 120 * 196 * 4 + 2048)

__global__ void __launch_bounds__(512, 1)
cheb_mma_kernel(const float* __restrict__ zin, int T,
                const u32* __restrict__ Cw, const float* __restrict__ cb,
                float* __restrict__ out) {
    extern __shared__ char smraw[];
    __shared__ float Lsm[NPAD * NPAD], L2sm[NPAD * NPAD];
    __shared__ float sbias[64];

    const u32 sb0 = smem_u32(smraw);
    const u32 sbase = (sb0 + 1023) & ~1023u;
    char* sm = smraw + (sbase - sb0);
    float* Yf = (float*)(sm + CH_OFF_Y);

    const int tid = threadIdx.x;
    const int wid = tid >> 5, lane = tid & 31;

    for (int i = tid; i < 12288; i += 512) {
        int s = i / 6144;
        int rem = i - s * 6144;
        int dg = rem >> 5, c2 = rem & 31;
        u32 byte = dg * 128 + c2 * 4;
        *(u32*)(sm + CH_OFF_W + s * 24576 + (byte ^ ((byte >> 3) & 0x70))) = Cw[i];
    }
    for (int i = tid; i < NPAD * NPAD; i += 512) { Lsm[i] = g_L[i]; L2sm[i] = g_L2[i]; }
    if (tid < 64) sbias[tid] = cb[tid];
    __syncthreads();

    const int ntt = (T + 2) / 3;
    const int ntiles = ntt * BATCH;

    const int mg = wid & 3;          // m32 group
    const int og = wid >> 2;         // n48 group
    const u32 a_row_l = lane & 15;
    const u32 a_koff  = (lane & 16) ? 16u : 0u;
    const u32 b_row_l = lane & 7;
    const u32 b_koff  = (lane & 8) ? 16u : 0u;
    const u32 b_sreg  = (lane & 16) ? 24576u : 0u;
    const int trow = lane >> 2, tcol = (lane & 3) * 2;

    const u64 bias2 = pk2(sbias[2 * lane], sbias[2 * lane + 1]);

    // mixing node assignment: warp w handles nodes w, w+16, w+32(<33)
    int nrow[3], nv = 0;
#pragma unroll
    for (int j = 0; j < 3; j++) {
        int n = wid + 16 * j;
        if (n < NNODE) nrow[nv++] = n;
    }

    for (int tile = blockIdx.x; tile < ntiles; tile += gridDim.x) {
        const int b  = tile / ntt;
        const int t0 = (tile % ntt) * 3;
        const size_t bbase = ((size_t)b * T + t0) * NSTR;

        __syncthreads();

        // ---- fill: Z bf16 hi/lo only (no fp32 copy, no prop) ----
        for (int i4 = tid; i4 < 120 * 16; i4 += 512) {
            int r = i4 >> 4, c4 = (i4 & 15) << 2;
            float4 v = *(const float4*)(zin + (bbase + r) * 64 + c4);
            __nv_bfloat16 hx = __float2bfloat16(v.x), hy = __float2bfloat16(v.y);
            __nv_bfloat16 hz = __float2bfloat16(v.z), hw = __float2bfloat16(v.w);
            u32 byte = r * 128 + (c4 << 1);
            u32 sw = byte ^ ((byte >> 3) & 0x70);
            *(u64*)(sm + CH_OFF_A + sw) = pack4bf(hx, hy, hz, hw);
            __nv_bfloat16 lx = __float2bfloat16(v.x - __bfloat162float(hx));
            __nv_bfloat16 ly = __float2bfloat16(v.y - __bfloat162float(hy));
            __nv_bfloat16 lz = __float2bfloat16(v.z - __bfloat162float(hz));
            __nv_bfloat16 lw = __float2bfloat16(v.w - __bfloat162float(hw));
            *(u64*)(sm + CH_OFF_A + 16384 + sw) = pack4bf(lx, ly, lz, lw);
        }
        __syncthreads();

        // ---- GEMM: Y[128x192] = Z[128x64] * Veff[64x192], bf16 hi/lo 3-pass ----
        float acc[2][6][4];
#pragma unroll
        for (int mi = 0; mi < 2; mi++)
#pragma unroll
            for (int ot = 0; ot < 6; ot++)
#pragma unroll
                for (int c = 0; c < 4; c++) acc[mi][ot][c] = 0.f;

#pragma unroll
        for (int kc = 0; kc < 4; kc++) {
            u32 ah[2][4], al[2][4];
#pragma unroll
            for (int mi = 0; mi < 2; mi++) {
                u32 rb = (u32)(mg * 32 + mi * 16) + a_row_l;
                u32 byte = rb * 128 + (u32)(kc * 32) + a_koff;
                u32 sw = byte ^ ((byte >> 3) & 0x70);
                ldsm_x4(ah[mi], sbase + CH_OFF_A + sw);
                ldsm_x4(al[mi], sbase + CH_OFF_A + 16384u + sw);
            }
#pragma unroll
            for (int ot = 0; ot < 6; ot++) {
                u32 bf[4];
                u32 nr = (u32)(og * 48 + 8 * ot) + b_row_l;
                u32 byte = nr * 128 + (u32)(kc * 32) + b_koff;
                ldsm_x4(bf, sbase + CH_OFF_W + b_sreg + (byte ^ ((byte >> 3) & 0x70)));
#pragma unroll
                for (int mi = 0; mi < 2; mi++) {
                    mma_bf16(acc[mi][ot], ah[mi], bf[0], bf[1]);
                    mma_bf16(acc[mi][ot], al[mi], bf[0], bf[1]);
                    mma_bf16(acc[mi][ot], ah[mi], bf[2], bf[3]);
                }
            }
        }

        // ---- Y store (fp32, stride 196 to avoid bank aliasing) ----
#pragma unroll
        for (int mi = 0; mi < 2; mi++)
#pragma unroll
            for (int rs = 0; rs < 2; rs++) {
                int r = mg * 32 + mi * 16 + trow + rs * 8;
                if (r < 120) {
                    float* yp = Yf + r * CH_YSTR + og * 48;
#pragma unroll
                    for (int ot = 0; ot < 6; ot++)
                        *(float2*)(yp + 8 * ot + tcol) =
                            make_float2(acc[mi][ot][rs * 2], acc[mi][ot][rs * 2 + 1]);
                }
            }
        __syncthreads();

        // ---- mixing: out = relu(Y0 + L*Y1 + L2*Y2 + bias), exact fp32 ----
#pragma unroll
        for (int t = 0; t < 3; t++) {
            if (t0 + t >= T) break;
            u64 acc2[3];
#pragma unroll
            for (int j = 0; j < 3; j++)
                if (j < nv)
                    acc2[j] = *(const u64*)(Yf + (t * 40 + nrow[j]) * CH_YSTR + 2 * lane);
            const float* yt = Yf + (t * 40) * CH_YSTR + 2 * lane;
            for (int m = 0; m < NNODE; m++) {
                u64 z1 = *(const u64*)(yt + m * CH_YSTR + 64);
                u64 z2 = *(const u64*)(yt + m * CH_YSTR + 128);
#pragma unroll
                for (int j = 0; j < 3; j++) {
                    if (j < nv) {
                        fma2(acc2[j], z1, dup2(Lsm[nrow[j] * NPAD + m]));
                        fma2(acc2[j], z2, dup2(L2sm[nrow[j] * NPAD + m]));
                    }
                }
            }
#pragma unroll
            for (int j = 0; j < 3; j++) {
                if (j < nv) {
                    float f0, f1, b0, b1;
                    unpk2(acc2[j], f0, f1);
                    unpk2(bias2, b0, b1);
                    float2 hv = make_float2(fmaxf(f0 + b0, 0.f), fmaxf(f1 + b1, 0.f));
                    *(float2*)(out + (bbase + t * 40 + nrow[j]) * 64 + 2 * lane) = hv;
                }
            }
        }
    }
}

// ---------------- BN stats ----------------
__global__ void __launch_bounds__(256)
bnstats_kernel(const float* __restrict__ x, int T,
               double* __restrict__ bnsum, double* __restrict__ bnsqs) {
    const int n = blockIdx.x, b = blockIdx.y, tid = threadIdx.x;
    const float* xp = x + ((size_t)b * T * NSTR + n) * 64;
    double s = 0.0, q = 0.0;
    for (int i = tid; i < T * 16; i += 256) {
        int t = i >> 4, c4 = (i & 15) << 2;
        float4 v = *(const float4*)(xp + (size_t)t * NSTR * 64 + c4);
        s += (double)v.x + (double)v.y + (double)v.z + (double)v.w;
        q += (double)v.x * v.x + (double)v.y * v.y + (double)v.z * v.z + (double)v.w * v.w;
    }
    __shared__ double r1[256], r2[256];
    r1[tid] = s; r2[tid] = q;
    __syncthreads();
    for (int st = 128; st > 0; st >>= 1) {
        if (tid < st) { r1[tid] += r1[tid + st]; r2[tid] += r2[tid + st]; }
        __syncthreads();
    }
    if (tid == 0) {
        atomicAdd(&bnsum[n], r1[0]);
        atomicAdd(&bnsqs[n], r2[0]);
    }
}

// ---------------- BN finalize ----------------
__global__ void finalize_bn_kernel(const double* __restrict__ sum, const double* __restrict__ sqs,
                                   const float* __restrict__ gamma, const float* __restrict__ beta,
                                   double cnt, float* __restrict__ scl, float* __restrict__ shf) {
    int nn = threadIdx.x;
    if (nn < NNODE) {
        double m = sum[nn] / cnt;
        double v = sqs[nn] / cnt - m * m;
        double inv = 1.0 / sqrt(v + 1e-5);
        double sc = (double)gamma[nn] * inv;
        scl[nn] = (float)sc;
        shf[nn] = (float)((double)beta[nn] - m * sc);
    }
}

// ---------------- fused BN+relu+time-mean ----------------
__global__ void timemean_kernel(const float* __restrict__ x, int T,
                                const float* __restrict__ scl, const float* __restrict__ shf) {
    const int n = blockIdx.x, b = blockIdx.y, c = threadIdx.x;
    const float sc = scl[n], sh = shf[n];
    double s = 0.0;
#pragma unroll 4
    for (int t = 0; t < T; t++) {
        float v = x[(((size_t)b * T + t) * NSTR + n) * CH + c];
        v = fmaxf(fmaf(v, sc, sh), 0.f);
        s += (double)v;
    }
    g_M[(b * NNODE + n) * CH + c] = (float)(s / (double)T);
}

// ---------------- classifier ----------------
__global__ void __launch_bounds__(256)
fc_kernel(const float* __restrict__ w1, const float* __restrict__ b1,
          const float* __restrict__ w2, const float* __restrict__ b2,
          float* __restrict__ out) {
    __shared__ float ms[NNODE * CH];
    __shared__ float h1[256];
    const int b = blockIdx.x, tid = threadIdx.x;
    for (int i = tid; i < NNODE * CH; i += 256) ms[i] = g_M[b * NNODE * CH + i];
    __syncthreads();
    double acc = (double)b1[tid];
    for (int i = 0; i < NNODE * CH; i++) acc += (double)ms[i] * (double)w1[i * 256 + tid];
    h1[tid] = fmaxf((float)acc, 0.f);
    __syncthreads();
    if (tid < 10) {
        double a2 = (double)b2[tid];
        for (int i = 0; i < 256; i++) a2 += (double)h1[i] * (double)w2[i * 10 + tid];
        out[b * 10 + tid] = (float)a2;
    }
}

// ---------------- launch ----------------
extern "C" void kernel_launch(void* const* d_in, const int* in_sizes, int n_in,
                              void* d_out, int out_size) {
    const float* x        = (const float*)d_in[0];
    const int*   ei       = (const int*)d_in[1];
    const float* s1_tc1_w = (const float*)d_in[2];
    const float* s1_tc1_b = (const float*)d_in[3];
    const float* s1_cheb_w= (const float*)d_in[4];
    const float* s1_cheb_b= (const float*)d_in[5];
    const float* s1_tc2_w = (const float*)d_in[6];
    const float* s1_tc2_b = (const float*)d_in[7];
    const float* s1_bn_g  = (const float*)d_in[8];
    const float* s1_bn_b  = (const float*)d_in[9];
    const float* s2_tc1_w = (const float*)d_in[10];
    const float* s2_tc1_b = (const float*)d_in[11];
    const float* s2_cheb_w= (const float*)d_in[12];
    const float* s2_cheb_b= (const float*)d_in[13];
    const float* s2_tc2_w = (const float*)d_in[14];
    const float* s2_tc2_b = (const float*)d_in[15];
    const float* s2_bn_g  = (const float*)d_in[16];
    const float* s2_bn_b  = (const float*)d_in[17];
    const float* fc1_w    = (const float*)d_in[18];
    const float* fc1_b    = (const float*)d_in[19];
    const float* fc2_w    = (const float*)d_in[20];
    const float* fc2_b    = (const float*)d_in[21];

    float *bufA, *bufB, *scl1, *shf1, *scl2, *shf2;
    u32 *Bw1, *Bw2, *Bw3, *Cw1, *Cw2;
    double *sum1, *sqs1, *sum2, *sqs2;
    cudaGetSymbolAddress((void**)&bufA, g_bufA);
    cudaGetSymbolAddress((void**)&bufB, g_bufB);
    cudaGetSymbolAddress((void**)&Bw1, g_Bw1);
    cudaGetSymbolAddress((void**)&Bw2, g_Bw2);
    cudaGetSymbolAddress((void**)&Bw3, g_Bw3);
    cudaGetSymbolAddress((void**)&Cw1, g_Cw1);
    cudaGetSymbolAddress((void**)&Cw2, g_Cw2);
    cudaGetSymbolAddress((void**)&scl1, g_scl1);
    cudaGetSymbolAddress((void**)&shf1, g_shf1);
    cudaGetSymbolAddress((void**)&scl2, g_scl2);
    cudaGetSymbolAddress((void**)&shf2, g_shf2);
    cudaGetSymbolAddress((void**)&sum1, g_sum1);
    cudaGetSymbolAddress((void**)&sqs1, g_sqs1);
    cudaGetSymbolAddress((void**)&sum2, g_sum2);
    cudaGetSymbolAddress((void**)&sqs2, g_sqs2);

    cudaFuncSetAttribute(tconv_mma_kernel, cudaFuncAttributeMaxDynamicSharedMemorySize, TC_SMEM);
    cudaFuncSetAttribute(cheb_mma_kernel,  cudaFuncAttributeMaxDynamicSharedMemorySize, CH_DYN);

    const int ne = in_sizes[1] / 2;
    const int GRID = 148;

    // launch order: profiled launch (index 3) = first cheb_mma
    setup_kernel<<<1, 64>>>(ei, ne, s1_tc1_w);                                        // 0
    tconv3_kernel<<<GRID, dim3(64, 8)>>>(x, s1_tc1_b, bufA);                          // 1: T=510
    convert_cw_kernel<<<96, 256>>>(s1_cheb_w, Cw1, s2_cheb_w, Cw2);                   // 2
    cheb_mma_kernel<<<GRID, 512, CH_DYN>>>(bufA, 510, Cw1, s1_cheb_b, bufB);          // 3 (profiled)
    convert_w_kernel<<<144, 256>>>(s1_tc2_w, Bw1);                                    // 4
    tconv_mma_kernel<<<GRID, 512, TC_SMEM>>>(bufB, 510, Bw1, s1_tc2_b,
                                             nullptr, nullptr, 0, bufA);              // 5: T=508
    convert_w_kernel<<<144, 256>>>(s2_tc1_w, Bw2);                                    // 6
    bnstats_kernel<<<dim3(NNODE, BATCH), 256>>>(bufA, 508, sum1, sqs1);               // 7
    finalize_bn_kernel<<<1, 64>>>(sum1, sqs1, s1_bn_g, s1_bn_b,
                                  (double)BATCH * 508.0 * 64.0, scl1, shf1);          // 8

    // ---- STConv 2 (BN1+relu fused into A-conversion) ----
    tconv_mma_kernel<<<GRID, 512, TC_SMEM>>>(bufA, 508, Bw2, s2_tc1_b,
                                             scl1, shf1, 1, bufB);                    // 9: T=506
    convert_w_kernel<<<144, 256>>>(s2_tc2_w, Bw3);                                    // 10
    cheb_mma_kernel<<<GRID, 512, CH_DYN>>>(bufB, 506, Cw2, s2_cheb_b, bufA);          // 11
    tconv_mma_kernel<<<GRID, 512, TC_SMEM>>>(bufA, 506, Bw3, s2_tc2_b,
                                             nullptr, nullptr, 0, bufB);              // 12: T=504
    bnstats_kernel<<<dim3(NNODE, BATCH), 256>>>(bufB, 504, sum2, sqs2);               // 13
    finalize_bn_kernel<<<1, 64>>>(sum2, sqs2, s2_bn_g, s2_bn_b,
                                  (double)BATCH * 504.0 * 64.0, scl2, shf2);          // 14

    // ---- head ----
    timemean_kernel<<<dim3(NNODE, BATCH), 64>>>(bufB, 504, scl2, shf2);               // 15
    fc_kernel<<<BATCH, 256>>>(fc1_w, fc1_b, fc2_w, fc2_b, (float*)d_out);             // 16
}

// round 11
// speedup vs baseline: 1.0517x; 1.0517x over previous
#include <cuda_runtime.h>
#include <cuda_bf16.h>
#include <math.h>

#define BATCH 32
#define NNODE 33
#define NSTR  40
#define NPAD  36
#define CH    64

typedef unsigned long long u64;
typedef unsigned int u32;
typedef unsigned short u16;

// ---------------- f32x2 helpers ----------------
__device__ __forceinline__ u64 pk2(float lo, float hi) {
    u64 r;
    asm("mov.b64 %0, {%1, %2};" : "=l"(r) : "r"(__float_as_uint(lo)), "r"(__float_as_uint(hi)));
    return r;
}
__device__ __forceinline__ u64 dup2(float v) { return pk2(v, v); }
__device__ __forceinline__ void unpk2(u64 v, float& lo, float& hi) {
    u32 a, b;
    asm("mov.b64 {%0, %1}, %2;" : "=r"(a), "=r"(b) : "l"(v));
    lo = __uint_as_float(a);
    hi = __uint_as_float(b);
}
__device__ __forceinline__ void fma2(u64& d, u64 a, u64 b) {
    asm("fma.rn.f32x2 %0, %1, %2, %0;" : "+l"(d) : "l"(a), "l"(b));
}

// ---------------- mma.sync / ldmatrix helpers ----------------
__device__ __forceinline__ u32 smem_u32(const void* p) {
    u32 a;
    asm("{ .reg .u64 t; cvta.to.shared.u64 t, %1; cvt.u32.u64 %0, t; }" : "=r"(a) : "l"(p));
    return a;
}
__device__ __forceinline__ void ldsm_x4(u32* r, u32 addr) {
    asm volatile("ldmatrix.sync.aligned.m8n8.x4.shared.b16 {%0,%1,%2,%3}, [%4];"
                 : "=r"(r[0]), "=r"(r[1]), "=r"(r[2]), "=r"(r[3]) : "r"(addr));
}
__device__ __forceinline__ void mma_bf16(float* c, const u32* a, u32 b0, u32 b1) {
    asm volatile("mma.sync.aligned.m16n8k16.row.col.f32.bf16.bf16.f32 "
                 "{%0,%1,%2,%3}, {%4,%5,%6,%7}, {%8,%9}, {%0,%1,%2,%3};"
                 : "+f"(c[0]), "+f"(c[1]), "+f"(c[2]), "+f"(c[3])
                 : "r"(a[0]), "r"(a[1]), "r"(a[2]), "r"(a[3]), "r"(b0), "r"(b1));
}
__device__ __forceinline__ u64 pack4bf(__nv_bfloat16 a, __nv_bfloat16 b,
                                       __nv_bfloat16 c, __nv_bfloat16 d) {
    u32 u0 = ((u32)__bfloat16_as_ushort(b) << 16) | (u32)__bfloat16_as_ushort(a);
    u32 u1 = ((u32)__bfloat16_as_ushort(d) << 16) | (u32)__bfloat16_as_ushort(c);
    return (u64)u0 | ((u64)u1 << 32);
}
__device__ __forceinline__ void bfsplit(float v, u16& h, u16& l) {
    __nv_bfloat16 hb = __float2bfloat16(v);
    h = __bfloat16_as_ushort(hb);
    l = __bfloat16_as_ushort(__float2bfloat16(v - __bfloat162float(hb)));
}

// ---------------- device scratch ----------------
#define BUF_ELEMS ((size_t)BATCH * 510 * NSTR * CH)
__device__ float g_bufA[BUF_ELEMS];
__device__ float g_bufB[BUF_ELEMS];
__device__ float g_L[NPAD * NPAD];
__device__ float g_L2[NPAD * NPAD];
__device__ float g_w1a[3 * 3 * 3 * 64];
__device__ u32   g_Bw1[36864], g_Bw2[36864], g_Bw3[36864];
__device__ u32   g_Cw1[12288], g_Cw2[12288];
__device__ float g_scl1[NNODE], g_shf1[NNODE];
__device__ float g_scl2[NNODE], g_shf2[NNODE];
__device__ double g_sum1[NNODE], g_sqs1[NNODE];
__device__ double g_sum2[NNODE], g_sqs2[NNODE];
__device__ float g_M[BATCH * NNODE * CH];

// ---------------- setup ----------------
__global__ void setup_kernel(const int* __restrict__ ei, int ne, const float* __restrict__ w3) {
    __shared__ float sL[NPAD * NPAD];
    int i = threadIdx.x;
    if (i < NNODE) { g_sum1[i] = 0.0; g_sqs1[i] = 0.0; g_sum2[i] = 0.0; g_sqs2[i] = 0.0; }
    for (int j = i; j < 3 * 3 * 3 * 64; j += 64) {
        int o  = j & 63;
        int k  = (j >> 6) % 3;
        int ci = (j / 192) % 3;
        int g  = j / (192 * 3);
        g_w1a[j] = w3[((g * 64 + o) * 3 + ci) * 3 + k];
    }
    if (i == 0) {
        double deg[NNODE];
        for (int k = 0; k < NNODE; k++) deg[k] = 0.0;
        for (int e = 0; e < ne; e++) deg[ei[e]] += 1.0;
        double dinv[NNODE];
        for (int k = 0; k < NNODE; k++) dinv[k] = (deg[k] > 0.0) ? (1.0 / sqrt(deg[k])) : 0.0;
        for (int k = 0; k < NPAD * NPAD; k++) sL[k] = 0.0f;
        for (int e = 0; e < ne; e++) {
            int s = ei[e];
            int t = ei[ne + e];
            sL[t * NPAD + s] += (float)(-dinv[s] * dinv[t]);
        }
        for (int k = 0; k < NPAD * NPAD; k++) g_L[k] = sL[k];
    }
    __syncthreads();
    for (int idx = i; idx < NPAD * NPAD; idx += 64) {
        int r = idx / NPAD, c = idx % NPAD;
        float s = 0.f;
        for (int m = 0; m < NPAD; m++) s = fmaf(sL[r * NPAD + m], sL[m * NPAD + c], s);
        g_L2[idx] = s;
    }
}

// ---- tconv weights -> bf16 hi/lo regions ----
__global__ void convert_w_kernel(const float* __restrict__ w, u32* __restrict__ outw) {
    int i = blockIdx.x * blockDim.x + threadIdx.x;
    if (i >= 36864) return;
    int region = i >> 11;
    int rem    = i & 2047;
    int o      = rem >> 5;
    int c2     = rem & 31;
    int s  = region & 1;
    int gk = region >> 1;
    int g  = gk / 3, k = gk % 3;
    int ci0 = 2 * c2;
    float v0 = w[((g * 64 + o) * 64 + ci0) * 3 + k];
    float v1 = w[((g * 64 + o) * 64 + ci0 + 1) * 3 + k];
    u16 h0, l0, h1, l1;
    bfsplit(v0, h0, l0);
    bfsplit(v1, h1, l1);
    outw[i] = (s == 0) ? (((u32)h1 << 16) | (u32)h0) : (((u32)l1 << 16) | (u32)l0);
}

// ---- cheb weights -> flat Veff [s][dg=k*64+d][c-pair], Veff = [W0-W2, W1, 2*W2] ----
__device__ __forceinline__ float veff(const float* cw, int k, int c, int d) {
    if (k == 0) return cw[(0 * 64 + c) * 64 + d] - cw[(2 * 64 + c) * 64 + d];
    if (k == 1) return cw[(1 * 64 + c) * 64 + d];
    return 2.f * cw[(2 * 64 + c) * 64 + d];
}
__global__ void convert_cw_kernel(const float* __restrict__ cw1, u32* __restrict__ o1,
                                  const float* __restrict__ cw2, u32* __restrict__ o2) {
    int i = blockIdx.x * blockDim.x + threadIdx.x;
    if (i >= 24576) return;
    const float* cw = (i < 12288) ? cw1 : cw2;
    u32* op = (i < 12288) ? o1 : o2;
    int j = (i < 12288) ? i : (i - 12288);
    int s   = j / 6144;
    int rem = j - s * 6144;
    int dg  = rem >> 5, c2 = rem & 31;
    int k = dg >> 6, d = dg & 63, c0 = 2 * c2;
    float v0 = veff(cw, k, c0, d);
    float v1 = veff(cw, k, c0 + 1, d);
    u16 h0, l0, h1, l1;
    bfsplit(v0, h0, l0);
    bfsplit(v1, h1, l1);
    op[j] = (s == 0) ? (((u32)h1 << 16) | (u32)h0) : (((u32)l1 << 16) | (u32)l0);
}

// ---------------- SIMT gated tconv CI=3 (first layer) ----------------
__global__ void __launch_bounds__(512)
tconv3_kernel(const float* __restrict__ xin,
              const float* __restrict__ bias,
              float* __restrict__ out) {
    constexpr int CI = 3, CT = 128, TO = 16, ST = CT + 4, HP = TO / 2;
    constexpr int Tin = 512, Tout = 510;
    __shared__ float ws[3 * CI * 3 * 64];
    __shared__ float xs[CI * ST];

    const int tid = threadIdx.y * 64 + threadIdx.x;
    const int ntch = (Tout + CT - 1) / CT;
    const int ntiles = ntch * NNODE * BATCH;

    for (int i = tid; i < 3 * CI * 3 * 64; i += 512) ws[i] = g_w1a[i];

    const int o  = threadIdx.x;
    const int tb = threadIdx.y * TO;
    const float bP = bias[o], bQ = bias[64 + o], bR = bias[128 + o];

    for (int tile = blockIdx.x; tile < ntiles; tile += gridDim.x) {
        const int tch = tile % ntch;
        const int rem = tile / ntch;
        const int n   = rem % NNODE;
        const int b   = rem / NNODE;
        const int t0  = tch * CT;

        __syncthreads();
        for (int i = tid; i < (CT + 2) * CI; i += 512) {
            int tt = i / CI, ci = i % CI;
            int t = t0 + tt;
            float v = 0.f;
            if (t < Tin) v = xin[(((size_t)b * Tin + t) * NNODE + n) * CI + ci];
            xs[ci * ST + tt] = v;
        }
        __syncthreads();

        u64 accP[3][HP];
#pragma unroll
        for (int g = 0; g < 3; g++)
#pragma unroll
            for (int p = 0; p < HP; p++) accP[g][p] = 0ull;

#pragma unroll
        for (int ci = 0; ci < CI; ci++) {
            const float* xp = &xs[ci * ST + tb];
            u64 ep[HP + 1];
#pragma unroll
            for (int p = 0; p <= HP; p++) ep[p] = *reinterpret_cast<const u64*>(xp + 2 * p);
            float xl[HP + 1], xh[HP + 1];
#pragma unroll
            for (int p = 0; p <= HP; p++) unpk2(ep[p], xl[p], xh[p]);
            u64 op[HP];
#pragma unroll
            for (int p = 0; p < HP; p++) op[p] = pk2(xh[p], xl[p + 1]);

#pragma unroll
            for (int g = 0; g < 3; g++) {
#pragma unroll
                for (int k = 0; k < 3; k++) {
                    u64 wd = dup2(ws[((g * CI + ci) * 3 + k) * 64 + o]);
                    const u64* xq = (k == 0) ? ep : (k == 1) ? op : (ep + 1);
#pragma unroll
                    for (int p = 0; p < HP; p++) fma2(accP[g][p], xq[p], wd);
                }
            }
        }

#pragma unroll
        for (int p = 0; p < HP; p++) {
            float P0, P1, Q0, Q1, R0, R1;
            unpk2(accP[0][p], P0, P1);
            unpk2(accP[1][p], Q0, Q1);
            unpk2(accP[2][p], R0, R1);
#pragma unroll
            for (int half = 0; half < 2; half++) {
                int t = t0 + tb + 2 * p + half;
                if (t < Tout) {
                    float P = (half ? P1 : P0) + bP;
                    float Q = (half ? Q1 : Q0) + bQ;
                    float R = (half ? R1 : R0) + bR;
                    float sg = 1.f / (1.f + __expf(-Q));
                    float h = fmaxf(fmaf(P, sg, R), 0.f);
                    out[(((size_t)b * Tout + t) * NSTR + n) * CH + o] = h;
                }
            }
        }
    }
}

// ---------------- mma.sync gated tconv CI=64 (512 threads, 16 warps) ----------------
#define ROWS_A 208
#define A_SPLIT_B (ROWS_A * 128)
#define B_BYTES   (18 * 8192)
#define OFF_B     1024
#define OFF_A     (OFF_B + B_BYTES)
#define TC_SMEM   (OFF_A + 2 * A_SPLIT_B + 1024)

__global__ void __launch_bounds__(512, 1)
tconv_mma_kernel(const float* __restrict__ xin, int Tin,
                 const u32* __restrict__ Bw,
                 const float* __restrict__ bias,
                 const float* __restrict__ scl, const float* __restrict__ shf, int mode,
                 float* __restrict__ out) {
    extern __shared__ char smraw[];
    __shared__ float sbias[192];

    const u32 sb0 = smem_u32(smraw);
    const u32 sbase = (sb0 + 1023) & ~1023u;
    char* sm = smraw + (sbase - sb0);

    const int tid = threadIdx.x;
    const int wid = tid >> 5, lane = tid & 31;
    const int Tout = Tin - 2;
    const int RowsIn = Tin * NSTR, RowsOut = Tout * NSTR;
    const int ntb = (RowsOut + 127) / 128;
    const int ntiles = ntb * BATCH;

    for (int i = tid; i < 36864; i += 512) {
        int r = i >> 11, rem = i & 2047, row = rem >> 5, c2 = rem & 31;
        u32 byte = row * 128 + c2 * 4;
        *(u32*)(sm + OFF_B + r * 8192 + (byte ^ ((byte >> 3) & 0x70))) = Bw[i];
    }
    if (tid < 192) sbias[tid] = bias[tid];
    __syncthreads();

    const int warp_m = wid & 7;
    const int o0 = (wid >> 3) * 32;

    const u32 a_row_l = lane & 15;
    const u32 a_koff  = (lane & 16) ? 16u : 0u;
    const u32 b_row_l = lane & 7;
    const u32 b_koff  = (lane & 8) ? 16u : 0u;
    const u32 b_sreg  = (lane & 16) ? 8192u : 0u;

    const int trow = lane >> 2;
    const int tcol = (lane & 3) * 2;

    for (int tile = blockIdx.x; tile < ntiles; tile += gridDim.x) {
        const int bidx = tile / ntb, tl = tile % ntb;
        const int local0 = tl * 128;
        const float* xb = xin + (size_t)bidx * RowsIn * 64;

        __syncthreads();

        for (int i4 = tid; i4 < ROWS_A * 16; i4 += 512) {
            int r = i4 >> 4, c4 = (i4 & 15) << 2;
            int il = local0 + r;
            float4 v = make_float4(0.f, 0.f, 0.f, 0.f);
            if (il < RowsIn) {
                int n = il % NSTR;
                if (n < NNODE) {
                    v = *(const float4*)(xb + (size_t)il * 64 + c4);
                    if (mode) {
                        float sc = scl[n], sh = shf[n];
                        v.x = fmaxf(fmaf(v.x, sc, sh), 0.f);
                        v.y = fmaxf(fmaf(v.y, sc, sh), 0.f);
                        v.z = fmaxf(fmaf(v.z, sc, sh), 0.f);
                        v.w = fmaxf(fmaf(v.w, sc, sh), 0.f);
                    }
                }
            }
            __nv_bfloat16 hx = __float2bfloat16(v.x), hy = __float2bfloat16(v.y);
            __nv_bfloat16 hz = __float2bfloat16(v.z), hw = __float2bfloat16(v.w);
            u32 byte = r * 128 + (c4 << 1);
            u32 sw = byte ^ ((byte >> 3) & 0x70);
            *(u64*)(sm + OFF_A + sw) = pack4bf(hx, hy, hz, hw);
            __nv_bfloat16 lx = __float2bfloat16(v.x - __bfloat162float(hx));
            __nv_bfloat16 ly = __float2bfloat16(v.y - __bfloat162float(hy));
            __nv_bfloat16 lz = __float2bfloat16(v.z - __bfloat162float(hz));
            __nv_bfloat16 lw = __float2bfloat16(v.w - __bfloat162float(hw));
            *(u64*)(sm + OFF_A + A_SPLIT_B + sw) = pack4bf(lx, ly, lz, lw);
        }
        __syncthreads();

        float acc[3][4][4];
#pragma unroll
        for (int g = 0; g < 3; g++)
#pragma unroll
            for (int ot = 0; ot < 4; ot++)
#pragma unroll
                for (int c = 0; c < 4; c++) acc[g][ot][c] = 0.f;

#pragma unroll
        for (int tap = 0; tap < 3; tap++) {
#pragma unroll
            for (int kc = 0; kc < 4; kc++) {
                u32 ah[4], al[4];
                {
                    u32 rb = (u32)(tap * 40 + warp_m * 16) + a_row_l;
                    u32 byte = rb * 128 + (u32)(kc * 32) + a_koff;
                    u32 sw = byte ^ ((byte >> 3) & 0x70);
                    ldsm_x4(ah, sbase + OFF_A + sw);
                    ldsm_x4(al, sbase + OFF_A + A_SPLIT_B + sw);
                }
#pragma unroll
                for (int g = 0; g < 3; g++) {
                    u32 breg = sbase + OFF_B + (u32)((g * 3 + tap) * 2) * 8192 + b_sreg;
                    u32 bf[4][4];
#pragma unroll
                    for (int ot = 0; ot < 4; ot++) {
                        u32 byte = (u32)(o0 + 8 * ot + (int)b_row_l) * 128 + (u32)(kc * 32) + b_koff;
                        ldsm_x4(bf[ot], breg + (byte ^ ((byte >> 3) & 0x70)));
                    }
#pragma unroll
                    for (int ot = 0; ot < 4; ot++)
                        mma_bf16(acc[g][ot], ah, bf[ot][0], bf[ot][1]);
#pragma unroll
                    for (int ot = 0; ot < 4; ot++)
                        mma_bf16(acc[g][ot], al, bf[ot][0], bf[ot][1]);
#pragma unroll
                    for (int ot = 0; ot < 4; ot++)
                        mma_bf16(acc[g][ot], ah, bf[ot][2], bf[ot][3]);
                }
            }
        }

#pragma unroll
        for (int rs = 0; rs < 2; rs++) {
            int row = warp_m * 16 + trow + rs * 8;
            int ol = local0 + row;
            if (ol < RowsOut) {
                float* op = out + ((size_t)bidx * RowsOut + ol) * 64;
#pragma unroll
                for (int ot = 0; ot < 4; ot++) {
                    int o = o0 + 8 * ot + tcol;
                    float2 hv;
#pragma unroll
                    for (int e = 0; e < 2; e++) {
                        float P = acc[0][ot][rs * 2 + e] + sbias[o + e];
                        float Q = acc[1][ot][rs * 2 + e] + sbias[64 + o + e];
                        float R = acc[2][ot][rs * 2 + e] + sbias[128 + o + e];
                        float sg = 1.f / (1.f + __expf(-Q));
                        float hval = fmaxf(fmaf(P, sg, R), 0.f);
                        if (e == 0) hv.x = hval; else hv.y = hval;
                    }
                    *(float2*)(op + o) = hv;
                }
            }
        }
    }
}

// ---------------- cheb v4: GEMM-first + low-redundancy fp32 L-mixing ----------------
// mixing: 15 warps = (t:3) x (node-group:5 of 7); each Y1/Y2 row loaded once per warp,
// amortized over 7 node accumulators; L rows read as broadcast float4.
#define CH_OFF_W  0                     // Veff hi 24576 | lo 24576
#define CH_OFF_A  49152                 // Z hi 16384 | lo 16384
#define CH_OFF_Y  81920                 // Y: 120 x 196 f32
#define CH_YSTR   196
#define CH_DYN    (81920 + 120 * 196 * 4 + 2048)

__global__ void __launch_bounds__(512, 1)
cheb_mma_kernel(const float* __restrict__ zin, int T,
                const u32* __restrict__ Cw, const float* __restrict__ cb,
                float* __restrict__ out) {
    extern __shared__ char smraw[];
    __shared__ float Lsm[NPAD * NPAD], L2sm[NPAD * NPAD];
    __shared__ float sbias[64];

    const u32 sb0 = smem_u32(smraw);
    const u32 sbase = (sb0 + 1023) & ~1023u;
    char* sm = smraw + (sbase - sb0);
    float* Yf = (float*)(sm + CH_OFF_Y);

    const int tid = threadIdx.x;
    const int wid = tid >> 5, lane = tid & 31;

    for (int i = tid; i < 12288; i += 512) {
        int s = i / 6144;
        int rem = i - s * 6144;
        int dg = rem >> 5, c2 = rem & 31;
        u32 byte = dg * 128 + c2 * 4;
        *(u32*)(sm + CH_OFF_W + s * 24576 + (byte ^ ((byte >> 3) & 0x70))) = Cw[i];
    }
    for (int i = tid; i < NPAD * NPAD; i += 512) { Lsm[i] = g_L[i]; L2sm[i] = g_L2[i]; }
    if (tid < 64) sbias[tid] = cb[tid];
    __syncthreads();

    const int ntt = (T + 2) / 3;
    const int ntiles = ntt * BATCH;

    const int mg = wid & 3;          // m32 group (GEMM)
    const int og = wid >> 2;         // n48 group (GEMM)
    const u32 a_row_l = lane & 15;
    const u32 a_koff  = (lane & 16) ? 16u : 0u;
    const u32 b_row_l = lane & 7;
    const u32 b_koff  = (lane & 8) ? 16u : 0u;
    const u32 b_sreg  = (lane & 16) ? 24576u : 0u;
    const int trow = lane >> 2, tcol = (lane & 3) * 2;

    const u64 bias2 = pk2(sbias[2 * lane], sbias[2 * lane + 1]);

    // mixing assignment: warp = mt*5 + mgp, 15 warps active
    const int mt   = wid / 5;                       // t index (0..2) for wid<15
    const int mgp  = wid - mt * 5;                  // node group
    const int nb   = mgp * 7;                       // base node
    const int ncnt = (NNODE - nb < 7) ? (NNODE - nb) : 7;

    for (int tile = blockIdx.x; tile < ntiles; tile += gridDim.x) {
        const int b  = tile / ntt;
        const int t0 = (tile % ntt) * 3;
        const size_t bbase = ((size_t)b * T + t0) * NSTR;

        __syncthreads();

        // ---- fill: Z bf16 hi/lo ----
        for (int i4 = tid; i4 < 120 * 16; i4 += 512) {
            int r = i4 >> 4, c4 = (i4 & 15) << 2;
            float4 v = *(const float4*)(zin + (bbase + r) * 64 + c4);
            __nv_bfloat16 hx = __float2bfloat16(v.x), hy = __float2bfloat16(v.y);
            __nv_bfloat16 hz = __float2bfloat16(v.z), hw = __float2bfloat16(v.w);
            u32 byte = r * 128 + (c4 << 1);
            u32 sw = byte ^ ((byte >> 3) & 0x70);
            *(u64*)(sm + CH_OFF_A + sw) = pack4bf(hx, hy, hz, hw);
            __nv_bfloat16 lx = __float2bfloat16(v.x - __bfloat162float(hx));
            __nv_bfloat16 ly = __float2bfloat16(v.y - __bfloat162float(hy));
            __nv_bfloat16 lz = __float2bfloat16(v.z - __bfloat162float(hz));
            __nv_bfloat16 lw = __float2bfloat16(v.w - __bfloat162float(hw));
            *(u64*)(sm + CH_OFF_A + 16384 + sw) = pack4bf(lx, ly, lz, lw);
        }
        __syncthreads();

        // ---- GEMM: Y[128x192] = Z[128x64] * Veff[64x192] ----
        float acc[2][6][4];
#pragma unroll
        for (int mi = 0; mi < 2; mi++)
#pragma unroll
            for (int ot = 0; ot < 6; ot++)
#pragma unroll
                for (int c = 0; c < 4; c++) acc[mi][ot][c] = 0.f;

#pragma unroll
        for (int kc = 0; kc < 4; kc++) {
            u32 ah[2][4], al[2][4];
#pragma unroll
            for (int mi = 0; mi < 2; mi++) {
                u32 rb = (u32)(mg * 32 + mi * 16) + a_row_l;
                u32 byte = rb * 128 + (u32)(kc * 32) + a_koff;
                u32 sw = byte ^ ((byte >> 3) & 0x70);
                ldsm_x4(ah[mi], sbase + CH_OFF_A + sw);
                ldsm_x4(al[mi], sbase + CH_OFF_A + 16384u + sw);
            }
#pragma unroll
            for (int ot = 0; ot < 6; ot++) {
                u32 bf[4];
                u32 nr = (u32)(og * 48 + 8 * ot) + b_row_l;
                u32 byte = nr * 128 + (u32)(kc * 32) + b_koff;
                ldsm_x4(bf, sbase + CH_OFF_W + b_sreg + (byte ^ ((byte >> 3) & 0x70)));
#pragma unroll
                for (int mi = 0; mi < 2; mi++) {
                    mma_bf16(acc[mi][ot], ah[mi], bf[0], bf[1]);
                    mma_bf16(acc[mi][ot], al[mi], bf[0], bf[1]);
                    mma_bf16(acc[mi][ot], ah[mi], bf[2], bf[3]);
                }
            }
        }

        // ---- Y store (fp32, stride 196) ----
#pragma unroll
        for (int mi = 0; mi < 2; mi++)
#pragma unroll
            for (int rs = 0; rs < 2; rs++) {
                int r = mg * 32 + mi * 16 + trow + rs * 8;
                if (r < 120) {
                    float* yp = Yf + r * CH_YSTR + og * 48;
#pragma unroll
                    for (int ot = 0; ot < 6; ot++)
                        *(float2*)(yp + 8 * ot + tcol) =
                            make_float2(acc[mi][ot][rs * 2], acc[mi][ot][rs * 2 + 1]);
                }
            }
        __syncthreads();

        // ---- mixing: out = relu(Y0 + L*Y1 + L2*Y2 + bias), low-redundancy ----
        if (wid < 15 && t0 + mt < T) {
            u64 acc2[7];
#pragma unroll
            for (int j = 0; j < 7; j++)
                acc2[j] = (j < ncnt)
                    ? *(const u64*)(Yf + (mt * 40 + nb + j) * CH_YSTR + 2 * lane)
                    : 0ull;
            const float* yt = Yf + (mt * 40) * CH_YSTR + 2 * lane;
#pragma unroll 3
            for (int m4 = 0; m4 < NPAD; m4 += 4) {
                u64 y1[4], y2[4];
#pragma unroll
                for (int q = 0; q < 4; q++) {
                    y1[q] = *(const u64*)(yt + (m4 + q) * CH_YSTR + 64);
                    y2[q] = *(const u64*)(yt + (m4 + q) * CH_YSTR + 128);
                }
#pragma unroll
                for (int j = 0; j < 7; j++) {
                    if (j < ncnt) {
                        float4 lv  = *(const float4*)(&Lsm [(nb + j) * NPAD + m4]);
                        float4 l2v = *(const float4*)(&L2sm[(nb + j) * NPAD + m4]);
                        fma2(acc2[j], y1[0], dup2(lv.x));
                        fma2(acc2[j], y1[1], dup2(lv.y));
                        fma2(acc2[j], y1[2], dup2(lv.z));
                        fma2(acc2[j], y1[3], dup2(lv.w));
                        fma2(acc2[j], y2[0], dup2(l2v.x));
                        fma2(acc2[j], y2[1], dup2(l2v.y));
                        fma2(acc2[j], y2[2], dup2(l2v.z));
                        fma2(acc2[j], y2[3], dup2(l2v.w));
                    }
                }
            }
#pragma unroll
            for (int j = 0; j < 7; j++) {
                if (j < ncnt) {
                    float f0, f1, b0, b1;
                    unpk2(acc2[j], f0, f1);
                    unpk2(bias2, b0, b1);
                    float2 hv = make_float2(fmaxf(f0 + b0, 0.f), fmaxf(f1 + b1, 0.f));
                    *(float2*)(out + (bbase + mt * 40 + nb + j) * 64 + 2 * lane) = hv;
                }
            }
        }
    }
}

// ---------------- BN stats ----------------
__global__ void __launch_bounds__(256)
bnstats_kernel(const float* __restrict__ x, int T,
               double* __restrict__ bnsum, double* __restrict__ bnsqs) {
    const int n = blockIdx.x, b = blockIdx.y, tid = threadIdx.x;
    const float* xp = x + ((size_t)b * T * NSTR + n) * 64;
    double s = 0.0, q = 0.0;
    for (int i = tid; i < T * 16; i += 256) {
        int t = i >> 4, c4 = (i & 15) << 2;
        float4 v = *(const float4*)(xp + (size_t)t * NSTR * 64 + c4);
        s += (double)v.x + (double)v.y + (double)v.z + (double)v.w;
        q += (double)v.x * v.x + (double)v.y * v.y + (double)v.z * v.z + (double)v.w * v.w;
    }
    __shared__ double r1[256], r2[256];
    r1[tid] = s; r2[tid] = q;
    __syncthreads();
    for (int st = 128; st > 0; st >>= 1) {
        if (tid < st) { r1[tid] += r1[tid + st]; r2[tid] += r2[tid + st]; }
        __syncthreads();
    }
    if (tid == 0) {
        atomicAdd(&bnsum[n], r1[0]);
        atomicAdd(&bnsqs[n], r2[0]);
    }
}

// ---------------- BN finalize ----------------
__global__ void finalize_bn_kernel(const double* __restrict__ sum, const double* __restrict__ sqs,
                                   const float* __restrict__ gamma, const float* __restrict__ beta,
                                   double cnt, float* __restrict__ scl, float* __restrict__ shf) {
    int nn = threadIdx.x;
    if (nn < NNODE) {
        double m = sum[nn] / cnt;
        double v = sqs[nn] / cnt - m * m;
        double inv = 1.0 / sqrt(v + 1e-5);
        double sc = (double)gamma[nn] * inv;
        scl[nn] = (float)sc;
        shf[nn] = (float)((double)beta[nn] - m * sc);
    }
}

// ---------------- fused BN+relu+time-mean ----------------
__global__ void timemean_kernel(const float* __restrict__ x, int T,
                                const float* __restrict__ scl, const float* __restrict__ shf) {
    const int n = blockIdx.x, b = blockIdx.y, c = threadIdx.x;
    const float sc = scl[n], sh = shf[n];
    double s = 0.0;
#pragma unroll 4
    for (int t = 0; t < T; t++) {
        float v = x[(((size_t)b * T + t) * NSTR + n) * CH + c];
        v = fmaxf(fmaf(v, sc, sh), 0.f);
        s += (double)v;
    }
    g_M[(b * NNODE + n) * CH + c] = (float)(s / (double)T);
}

// ---------------- classifier ----------------
__global__ void __launch_bounds__(256)
fc_kernel(const float* __restrict__ w1, const float* __restrict__ b1,
          const float* __restrict__ w2, const float* __restrict__ b2,
          float* __restrict__ out) {
    __shared__ float ms[NNODE * CH];
    __shared__ float h1[256];
    const int b = blockIdx.x, tid = threadIdx.x;
    for (int i = tid; i < NNODE * CH; i += 256) ms[i] = g_M[b * NNODE * CH + i];
    __syncthreads();
    double acc = (double)b1[tid];
    for (int i = 0; i < NNODE * CH; i++) acc += (double)ms[i] * (double)w1[i * 256 + tid];
    h1[tid] = fmaxf((float)acc, 0.f);
    __syncthreads();
    if (tid < 10) {
        double a2 = (double)b2[tid];
        for (int i = 0; i < 256; i++) a2 += (double)h1[i] * (double)w2[i * 10 + tid];
        out[b * 10 + tid] = (float)a2;
    }
}

// ---------------- launch ----------------
extern "C" void kernel_launch(void* const* d_in, const int* in_sizes, int n_in,
                              void* d_out, int out_size) {
    const float* x        = (const float*)d_in[0];
    const int*   ei       = (const int*)d_in[1];
    const float* s1_tc1_w = (const float*)d_in[2];
    const float* s1_tc1_b = (const float*)d_in[3];
    const float* s1_cheb_w= (const float*)d_in[4];
    const float* s1_cheb_b= (const float*)d_in[5];
    const float* s1_tc2_w = (const float*)d_in[6];
    const float* s1_tc2_b = (const float*)d_in[7];
    const float* s1_bn_g  = (const float*)d_in[8];
    const float* s1_bn_b  = (const float*)d_in[9];
    const float* s2_tc1_w = (const float*)d_in[10];
    const float* s2_tc1_b = (const float*)d_in[11];
    const float* s2_cheb_w= (const float*)d_in[12];
    const float* s2_cheb_b= (const float*)d_in[13];
    const float* s2_tc2_w = (const float*)d_in[14];
    const float* s2_tc2_b = (const float*)d_in[15];
    const float* s2_bn_g  = (const float*)d_in[16];
    const float* s2_bn_b  = (const float*)d_in[17];
    const float* fc1_w    = (const float*)d_in[18];
    const float* fc1_b    = (const float*)d_in[19];
    const float* fc2_w    = (const float*)d_in[20];
    const float* fc2_b    = (const float*)d_in[21];

    float *bufA, *bufB, *scl1, *shf1, *scl2, *shf2;
    u32 *Bw1, *Bw2, *Bw3, *Cw1, *Cw2;
    double *sum1, *sqs1, *sum2, *sqs2;
    cudaGetSymbolAddress((void**)&bufA, g_bufA);
    cudaGetSymbolAddress((void**)&bufB, g_bufB);
    cudaGetSymbolAddress((void**)&Bw1, g_Bw1);
    cudaGetSymbolAddress((void**)&Bw2, g_Bw2);
    cudaGetSymbolAddress((void**)&Bw3, g_Bw3);
    cudaGetSymbolAddress((void**)&Cw1, g_Cw1);
    cudaGetSymbolAddress((void**)&Cw2, g_Cw2);
    cudaGetSymbolAddress((void**)&scl1, g_scl1);
    cudaGetSymbolAddress((void**)&shf1, g_shf1);
    cudaGetSymbolAddress((void**)&scl2, g_scl2);
    cudaGetSymbolAddress((void**)&shf2, g_shf2);
    cudaGetSymbolAddress((void**)&sum1, g_sum1);
    cudaGetSymbolAddress((void**)&sqs1, g_sqs1);
    cudaGetSymbolAddress((void**)&sum2, g_sum2);
    cudaGetSymbolAddress((void**)&sqs2, g_sqs2);

    cudaFuncSetAttribute(tconv_mma_kernel, cudaFuncAttributeMaxDynamicSharedMemorySize, TC_SMEM);
    cudaFuncSetAttribute(cheb_mma_kernel,  cudaFuncAttributeMaxDynamicSharedMemorySize, CH_DYN);

    const int ne = in_sizes[1] / 2;
    const int GRID = 148;

    // launch order: profiled launch (index 3) = first cheb_mma
    setup_kernel<<<1, 64>>>(ei, ne, s1_tc1_w);                                        // 0
    tconv3_kernel<<<GRID, dim3(64, 8)>>>(x, s1_tc1_b, bufA);                          // 1: T=510
    convert_cw_kernel<<<96, 256>>>(s1_cheb_w, Cw1, s2_cheb_w, Cw2);                   // 2
    cheb_mma_kernel<<<GRID, 512, CH_DYN>>>(bufA, 510, Cw1, s1_cheb_b, bufB);          // 3 (profiled)
    convert_w_kernel<<<144, 256>>>(s1_tc2_w, Bw1);                                    // 4
    tconv_mma_kernel<<<GRID, 512, TC_SMEM>>>(bufB, 510, Bw1, s1_tc2_b,
                                             nullptr, nullptr, 0, bufA);              // 5: T=508
    convert_w_kernel<<<144, 256>>>(s2_tc1_w, Bw2);                                    // 6
    bnstats_kernel<<<dim3(NNODE, BATCH), 256>>>(bufA, 508, sum1, sqs1);               // 7
    finalize_bn_kernel<<<1, 64>>>(sum1, sqs1, s1_bn_g, s1_bn_b,
                                  (double)BATCH * 508.0 * 64.0, scl1, shf1);          // 8

    // ---- STConv 2 (BN1+relu fused into A-conversion) ----
    tconv_mma_kernel<<<GRID, 512, TC_SMEM>>>(bufA, 508, Bw2, s2_tc1_b,
                                             scl1, shf1, 1, bufB);                    // 9: T=506
    convert_w_kernel<<<144, 256>>>(s2_tc2_w, Bw3);                                    // 10
    cheb_mma_kernel<<<GRID, 512, CH_DYN>>>(bufB, 506, Cw2, s2_cheb_b, bufA);          // 11
    tconv_mma_kernel<<<GRID, 512, TC_SMEM>>>(bufA, 506, Bw3, s2_tc2_b,
                                             nullptr, nullptr, 0, bufB);              // 12: T=504
    bnstats_kernel<<<dim3(NNODE, BATCH), 256>>>(bufB, 504, sum2, sqs2);               // 13
    finalize_bn_kernel<<<1, 64>>>(sum2, sqs2, s2_bn_g, s2_bn_b,
                                  (double)BATCH * 504.0 * 64.0, scl2, shf2);          // 14

    // ---- head ----
    timemean_kernel<<<dim3(NNODE, BATCH), 64>>>(bufB, 504, scl2, shf2);               // 15
    fc_kernel<<<BATCH, 256>>>(fc1_w, fc1_b, fc2_w, fc2_b, (float*)d_out);             // 16
}

// round 12
// speedup vs baseline: 1.2086x; 1.1492x over previous
#include <cuda_runtime.h>
#include <cuda_bf16.h>
#include <math.h>

#define BATCH 32
#define NNODE 33
#define NSTR  40
#define NPAD  36
#define CH    64

typedef unsigned long long u64;
typedef unsigned int u32;
typedef unsigned short u16;

// ---------------- f32x2 helpers ----------------
__device__ __forceinline__ u64 pk2(float lo, float hi) {
    u64 r;
    asm("mov.b64 %0, {%1, %2};" : "=l"(r) : "r"(__float_as_uint(lo)), "r"(__float_as_uint(hi)));
    return r;
}
__device__ __forceinline__ u64 dup2(float v) { return pk2(v, v); }
__device__ __forceinline__ void unpk2(u64 v, float& lo, float& hi) {
    u32 a, b;
    asm("mov.b64 {%0, %1}, %2;" : "=r"(a), "=r"(b) : "l"(v));
    lo = __uint_as_float(a);
    hi = __uint_as_float(b);
}
__device__ __forceinline__ void fma2(u64& d, u64 a, u64 b) {
    asm("fma.rn.f32x2 %0, %1, %2, %0;" : "+l"(d) : "l"(a), "l"(b));
}

// ---------------- mma.sync / ldmatrix helpers ----------------
__device__ __forceinline__ u32 smem_u32(const void* p) {
    u32 a;
    asm("{ .reg .u64 t; cvta.to.shared.u64 t, %1; cvt.u32.u64 %0, t; }" : "=r"(a) : "l"(p));
    return a;
}
__device__ __forceinline__ void ldsm_x4(u32* r, u32 addr) {
    asm volatile("ldmatrix.sync.aligned.m8n8.x4.shared.b16 {%0,%1,%2,%3}, [%4];"
                 : "=r"(r[0]), "=r"(r[1]), "=r"(r[2]), "=r"(r[3]) : "r"(addr));
}
__device__ __forceinline__ void mma_bf16(float* c, const u32* a, u32 b0, u32 b1) {
    asm volatile("mma.sync.aligned.m16n8k16.row.col.f32.bf16.bf16.f32 "
                 "{%0,%1,%2,%3}, {%4,%5,%6,%7}, {%8,%9}, {%0,%1,%2,%3};"
                 : "+f"(c[0]), "+f"(c[1]), "+f"(c[2]), "+f"(c[3])
                 : "r"(a[0]), "r"(a[1]), "r"(a[2]), "r"(a[3]), "r"(b0), "r"(b1));
}
__device__ __forceinline__ u64 pack4bf(__nv_bfloat16 a, __nv_bfloat16 b,
                                       __nv_bfloat16 c, __nv_bfloat16 d) {
    u32 u0 = ((u32)__bfloat16_as_ushort(b) << 16) | (u32)__bfloat16_as_ushort(a);
    u32 u1 = ((u32)__bfloat16_as_ushort(d) << 16) | (u32)__bfloat16_as_ushort(c);
    return (u64)u0 | ((u64)u1 << 32);
}
__device__ __forceinline__ void bfsplit(float v, u16& h, u16& l) {
    __nv_bfloat16 hb = __float2bfloat16(v);
    h = __bfloat16_as_ushort(hb);
    l = __bfloat16_as_ushort(__float2bfloat16(v - __bfloat162float(hb)));
}

// ---------------- device scratch ----------------
#define BUF_ELEMS ((size_t)BATCH * 510 * NSTR * CH)
__device__ float g_bufA[BUF_ELEMS];
__device__ float g_bufB[BUF_ELEMS];
__device__ float g_L[NPAD * NPAD];
__device__ float g_L2[NPAD * NPAD];
__device__ float g_w1a[3 * 3 * 3 * 64];
__device__ u32   g_Bw1[36864], g_Bw2[36864], g_Bw3[36864];
__device__ u32   g_Cw1[12288], g_Cw2[12288];
__device__ float g_scl1[NNODE], g_shf1[NNODE];
__device__ float g_scl2[NNODE], g_shf2[NNODE];
__device__ double g_sum1[NNODE], g_sqs1[NNODE];
__device__ double g_sum2[NNODE], g_sqs2[NNODE];
__device__ float g_M[BATCH * NNODE * CH];

// ---------------- setup ----------------
__global__ void setup_kernel(const int* __restrict__ ei, int ne, const float* __restrict__ w3) {
    __shared__ float sL[NPAD * NPAD];
    int i = threadIdx.x;
    if (i < NNODE) { g_sum1[i] = 0.0; g_sqs1[i] = 0.0; g_sum2[i] = 0.0; g_sqs2[i] = 0.0; }
    for (int j = i; j < 3 * 3 * 3 * 64; j += 64) {
        int o  = j & 63;
        int k  = (j >> 6) % 3;
        int ci = (j / 192) % 3;
        int g  = j / (192 * 3);
        g_w1a[j] = w3[((g * 64 + o) * 3 + ci) * 3 + k];
    }
    if (i == 0) {
        double deg[NNODE];
        for (int k = 0; k < NNODE; k++) deg[k] = 0.0;
        for (int e = 0; e < ne; e++) deg[ei[e]] += 1.0;
        double dinv[NNODE];
        for (int k = 0; k < NNODE; k++) dinv[k] = (deg[k] > 0.0) ? (1.0 / sqrt(deg[k])) : 0.0;
        for (int k = 0; k < NPAD * NPAD; k++) sL[k] = 0.0f;
        for (int e = 0; e < ne; e++) {
            int s = ei[e];
            int t = ei[ne + e];
            sL[t * NPAD + s] += (float)(-dinv[s] * dinv[t]);
        }
        for (int k = 0; k < NPAD * NPAD; k++) g_L[k] = sL[k];
    }
    __syncthreads();
    for (int idx = i; idx < NPAD * NPAD; idx += 64) {
        int r = idx / NPAD, c = idx % NPAD;
        float s = 0.f;
        for (int m = 0; m < NPAD; m++) s = fmaf(sL[r * NPAD + m], sL[m * NPAD + c], s);
        g_L2[idx] = s;
    }
}

// ---- tconv weights -> bf16 hi/lo regions ----
__global__ void convert_w_kernel(const float* __restrict__ w, u32* __restrict__ outw) {
    int i = blockIdx.x * blockDim.x + threadIdx.x;
    if (i >= 36864) return;
    int region = i >> 11;
    int rem    = i & 2047;
    int o      = rem >> 5;
    int c2     = rem & 31;
    int s  = region & 1;
    int gk = region >> 1;
    int g  = gk / 3, k = gk % 3;
    int ci0 = 2 * c2;
    float v0 = w[((g * 64 + o) * 64 + ci0) * 3 + k];
    float v1 = w[((g * 64 + o) * 64 + ci0 + 1) * 3 + k];
    u16 h0, l0, h1, l1;
    bfsplit(v0, h0, l0);
    bfsplit(v1, h1, l1);
    outw[i] = (s == 0) ? (((u32)h1 << 16) | (u32)h0) : (((u32)l1 << 16) | (u32)l0);
}

// ---- cheb weights -> flat Veff [s][dg=k*64+d][c-pair], Veff = [W0-W2, W1, 2*W2] ----
__device__ __forceinline__ float veff(const float* cw, int k, int c, int d) {
    if (k == 0) return cw[(0 * 64 + c) * 64 + d] - cw[(2 * 64 + c) * 64 + d];
    if (k == 1) return cw[(1 * 64 + c) * 64 + d];
    return 2.f * cw[(2 * 64 + c) * 64 + d];
}
__global__ void convert_cw_kernel(const float* __restrict__ cw1, u32* __restrict__ o1,
                                  const float* __restrict__ cw2, u32* __restrict__ o2) {
    int i = blockIdx.x * blockDim.x + threadIdx.x;
    if (i >= 24576) return;
    const float* cw = (i < 12288) ? cw1 : cw2;
    u32* op = (i < 12288) ? o1 : o2;
    int j = (i < 12288) ? i : (i - 12288);
    int s   = j / 6144;
    int rem = j - s * 6144;
    int dg  = rem >> 5, c2 = rem & 31;
    int k = dg >> 6, d = dg & 63, c0 = 2 * c2;
    float v0 = veff(cw, k, c0, d);
    float v1 = veff(cw, k, c0 + 1, d);
    u16 h0, l0, h1, l1;
    bfsplit(v0, h0, l0);
    bfsplit(v1, h1, l1);
    op[j] = (s == 0) ? (((u32)h1 << 16) | (u32)h0) : (((u32)l1 << 16) | (u32)l0);
}

// ---------------- SIMT gated tconv CI=3 (first layer) ----------------
__global__ void __launch_bounds__(512)
tconv3_kernel(const float* __restrict__ xin,
              const float* __restrict__ bias,
              float* __restrict__ out) {
    constexpr int CI = 3, CT = 128, TO = 16, ST = CT + 4, HP = TO / 2;
    constexpr int Tin = 512, Tout = 510;
    __shared__ float ws[3 * CI * 3 * 64];
    __shared__ float xs[CI * ST];

    const int tid = threadIdx.y * 64 + threadIdx.x;
    const int ntch = (Tout + CT - 1) / CT;
    const int ntiles = ntch * NNODE * BATCH;

    for (int i = tid; i < 3 * CI * 3 * 64; i += 512) ws[i] = g_w1a[i];

    const int o  = threadIdx.x;
    const int tb = threadIdx.y * TO;
    const float bP = bias[o], bQ = bias[64 + o], bR = bias[128 + o];

    for (int tile = blockIdx.x; tile < ntiles; tile += gridDim.x) {
        const int tch = tile % ntch;
        const int rem = tile / ntch;
        const int n   = rem % NNODE;
        const int b   = rem / NNODE;
        const int t0  = tch * CT;

        __syncthreads();
        for (int i = tid; i < (CT + 2) * CI; i += 512) {
            int tt = i / CI, ci = i % CI;
            int t = t0 + tt;
            float v = 0.f;
            if (t < Tin) v = xin[(((size_t)b * Tin + t) * NNODE + n) * CI + ci];
            xs[ci * ST + tt] = v;
        }
        __syncthreads();

        u64 accP[3][HP];
#pragma unroll
        for (int g = 0; g < 3; g++)
#pragma unroll
            for (int p = 0; p < HP; p++) accP[g][p] = 0ull;

#pragma unroll
        for (int ci = 0; ci < CI; ci++) {
            const float* xp = &xs[ci * ST + tb];
            u64 ep[HP + 1];
#pragma unroll
            for (int p = 0; p <= HP; p++) ep[p] = *reinterpret_cast<const u64*>(xp + 2 * p);
            float xl[HP + 1], xh[HP + 1];
#pragma unroll
            for (int p = 0; p <= HP; p++) unpk2(ep[p], xl[p], xh[p]);
            u64 op[HP];
#pragma unroll
            for (int p = 0; p < HP; p++) op[p] = pk2(xh[p], xl[p + 1]);

#pragma unroll
            for (int g = 0; g < 3; g++) {
#pragma unroll
                for (int k = 0; k < 3; k++) {
                    u64 wd = dup2(ws[((g * CI + ci) * 3 + k) * 64 + o]);
                    const u64* xq = (k == 0) ? ep : (k == 1) ? op : (ep + 1);
#pragma unroll
                    for (int p = 0; p < HP; p++) fma2(accP[g][p], xq[p], wd);
                }
            }
        }

#pragma unroll
        for (int p = 0; p < HP; p++) {
            float P0, P1, Q0, Q1, R0, R1;
            unpk2(accP[0][p], P0, P1);
            unpk2(accP[1][p], Q0, Q1);
            unpk2(accP[2][p], R0, R1);
#pragma unroll
            for (int half = 0; half < 2; half++) {
                int t = t0 + tb + 2 * p + half;
                if (t < Tout) {
                    float P = (half ? P1 : P0) + bP;
                    float Q = (half ? Q1 : Q0) + bQ;
                    float R = (half ? R1 : R0) + bR;
                    float sg = 1.f / (1.f + __expf(-Q));
                    float h = fmaxf(fmaf(P, sg, R), 0.f);
                    out[(((size_t)b * Tout + t) * NSTR + n) * CH + o] = h;
                }
            }
        }
    }
}

// ---------------- mma.sync gated tconv CI=64 (512 threads, 16 warps) ----------------
// dostats: fused BN statistics (quad shuffle -> shared float atomics -> global double)
#define ROWS_A 208
#define A_SPLIT_B (ROWS_A * 128)
#define B_BYTES   (18 * 8192)
#define OFF_B     1024
#define OFF_A     (OFF_B + B_BYTES)
#define TC_SMEM   (OFF_A + 2 * A_SPLIT_B + 1024)

__global__ void __launch_bounds__(512, 1)
tconv_mma_kernel(const float* __restrict__ xin, int Tin,
                 const u32* __restrict__ Bw,
                 const float* __restrict__ bias,
                 const float* __restrict__ scl, const float* __restrict__ shf, int mode,
                 float* __restrict__ out,
                 double* bnsum, double* bnsqs) {
    extern __shared__ char smraw[];
    __shared__ float sbias[192];
    __shared__ float sbn1[NNODE], sbn2[NNODE];

    const u32 sb0 = smem_u32(smraw);
    const u32 sbase = (sb0 + 1023) & ~1023u;
    char* sm = smraw + (sbase - sb0);

    const int tid = threadIdx.x;
    const int wid = tid >> 5, lane = tid & 31;
    const int Tout = Tin - 2;
    const int RowsIn = Tin * NSTR, RowsOut = Tout * NSTR;
    const int ntb = (RowsOut + 127) / 128;
    const int ntiles = ntb * BATCH;
    const int dostats = (bnsum != nullptr);

    for (int i = tid; i < 36864; i += 512) {
        int r = i >> 11, rem = i & 2047, row = rem >> 5, c2 = rem & 31;
        u32 byte = row * 128 + c2 * 4;
        *(u32*)(sm + OFF_B + r * 8192 + (byte ^ ((byte >> 3) & 0x70))) = Bw[i];
    }
    if (tid < 192) sbias[tid] = bias[tid];
    if (tid < NNODE) { sbn1[tid] = 0.f; sbn2[tid] = 0.f; }
    __syncthreads();

    const int warp_m = wid & 7;
    const int o0 = (wid >> 3) * 32;

    const u32 a_row_l = lane & 15;
    const u32 a_koff  = (lane & 16) ? 16u : 0u;
    const u32 b_row_l = lane & 7;
    const u32 b_koff  = (lane & 8) ? 16u : 0u;
    const u32 b_sreg  = (lane & 16) ? 8192u : 0u;

    const int trow = lane >> 2;
    const int tcol = (lane & 3) * 2;

    for (int tile = blockIdx.x; tile < ntiles; tile += gridDim.x) {
        const int bidx = tile / ntb, tl = tile % ntb;
        const int local0 = tl * 128;
        const float* xb = xin + (size_t)bidx * RowsIn * 64;

        __syncthreads();

        for (int i4 = tid; i4 < ROWS_A * 16; i4 += 512) {
            int r = i4 >> 4, c4 = (i4 & 15) << 2;
            int il = local0 + r;
            float4 v = make_float4(0.f, 0.f, 0.f, 0.f);
            if (il < RowsIn) {
                int n = il % NSTR;
                if (n < NNODE) {
                    v = *(const float4*)(xb + (size_t)il * 64 + c4);
                    if (mode) {
                        float sc = scl[n], sh = shf[n];
                        v.x = fmaxf(fmaf(v.x, sc, sh), 0.f);
                        v.y = fmaxf(fmaf(v.y, sc, sh), 0.f);
                        v.z = fmaxf(fmaf(v.z, sc, sh), 0.f);
                        v.w = fmaxf(fmaf(v.w, sc, sh), 0.f);
                    }
                }
            }
            __nv_bfloat16 hx = __float2bfloat16(v.x), hy = __float2bfloat16(v.y);
            __nv_bfloat16 hz = __float2bfloat16(v.z), hw = __float2bfloat16(v.w);
            u32 byte = r * 128 + (c4 << 1);
            u32 sw = byte ^ ((byte >> 3) & 0x70);
            *(u64*)(sm + OFF_A + sw) = pack4bf(hx, hy, hz, hw);
            __nv_bfloat16 lx = __float2bfloat16(v.x - __bfloat162float(hx));
            __nv_bfloat16 ly = __float2bfloat16(v.y - __bfloat162float(hy));
            __nv_bfloat16 lz = __float2bfloat16(v.z - __bfloat162float(hz));
            __nv_bfloat16 lw = __float2bfloat16(v.w - __bfloat162float(hw));
            *(u64*)(sm + OFF_A + A_SPLIT_B + sw) = pack4bf(lx, ly, lz, lw);
        }
        __syncthreads();

        float acc[3][4][4];
#pragma unroll
        for (int g = 0; g < 3; g++)
#pragma unroll
            for (int ot = 0; ot < 4; ot++)
#pragma unroll
                for (int c = 0; c < 4; c++) acc[g][ot][c] = 0.f;

#pragma unroll
        for (int tap = 0; tap < 3; tap++) {
#pragma unroll
            for (int kc = 0; kc < 4; kc++) {
                u32 ah[4], al[4];
                {
                    u32 rb = (u32)(tap * 40 + warp_m * 16) + a_row_l;
                    u32 byte = rb * 128 + (u32)(kc * 32) + a_koff;
                    u32 sw = byte ^ ((byte >> 3) & 0x70);
                    ldsm_x4(ah, sbase + OFF_A + sw);
                    ldsm_x4(al, sbase + OFF_A + A_SPLIT_B + sw);
                }
#pragma unroll
                for (int g = 0; g < 3; g++) {
                    u32 breg = sbase + OFF_B + (u32)((g * 3 + tap) * 2) * 8192 + b_sreg;
                    u32 bf[4][4];
#pragma unroll
                    for (int ot = 0; ot < 4; ot++) {
                        u32 byte = (u32)(o0 + 8 * ot + (int)b_row_l) * 128 + (u32)(kc * 32) + b_koff;
                        ldsm_x4(bf[ot], breg + (byte ^ ((byte >> 3) & 0x70)));
                    }
#pragma unroll
                    for (int ot = 0; ot < 4; ot++)
                        mma_bf16(acc[g][ot], ah, bf[ot][0], bf[ot][1]);
#pragma unroll
                    for (int ot = 0; ot < 4; ot++)
                        mma_bf16(acc[g][ot], al, bf[ot][0], bf[ot][1]);
#pragma unroll
                    for (int ot = 0; ot < 4; ot++)
                        mma_bf16(acc[g][ot], ah, bf[ot][2], bf[ot][3]);
                }
            }
        }

#pragma unroll
        for (int rs = 0; rs < 2; rs++) {
            int row = warp_m * 16 + trow + rs * 8;
            int ol = local0 + row;
            const bool valid = (ol < RowsOut);
            const int n = ol % NSTR;

            float hv[8];
            float s1 = 0.f, s2 = 0.f;
#pragma unroll
            for (int ot = 0; ot < 4; ot++) {
                int o = o0 + 8 * ot + tcol;
#pragma unroll
                for (int e = 0; e < 2; e++) {
                    float P = acc[0][ot][rs * 2 + e] + sbias[o + e];
                    float Q = acc[1][ot][rs * 2 + e] + sbias[64 + o + e];
                    float R = acc[2][ot][rs * 2 + e] + sbias[128 + o + e];
                    float sg = 1.f / (1.f + __expf(-Q));
                    float h = fmaxf(fmaf(P, sg, R), 0.f);
                    hv[2 * ot + e] = h;
                    s1 += h;
                    s2 += h * h;
                }
            }

            if (dostats) {
                if (!valid || n >= NNODE) { s1 = 0.f; s2 = 0.f; }
                s1 += __shfl_xor_sync(0xffffffffu, s1, 1);
                s1 += __shfl_xor_sync(0xffffffffu, s1, 2);
                s2 += __shfl_xor_sync(0xffffffffu, s2, 1);
                s2 += __shfl_xor_sync(0xffffffffu, s2, 2);
                if ((lane & 3) == 0 && valid && n < NNODE) {
                    atomicAdd(&sbn1[n], s1);
                    atomicAdd(&sbn2[n], s2);
                }
            }

            if (valid) {
                float* op = out + ((size_t)bidx * RowsOut + ol) * 64 + o0;
#pragma unroll
                for (int ot = 0; ot < 4; ot++)
                    *(float2*)(op + 8 * ot + tcol) = make_float2(hv[2 * ot], hv[2 * ot + 1]);
            }
        }
    }

    if (dostats) {
        __syncthreads();
        if (tid < NNODE) {
            atomicAdd(&bnsum[tid], (double)sbn1[tid]);
            atomicAdd(&bnsqs[tid], (double)sbn2[tid]);
        }
    }
}

// ---------------- cheb v4: GEMM-first + low-redundancy fp32 L-mixing (R11, unchanged) ----------------
#define CH_OFF_W  0
#define CH_OFF_A  49152
#define CH_OFF_Y  81920
#define CH_YSTR   196
#define CH_DYN    (81920 + 120 * 196 * 4 + 2048)

__global__ void __launch_bounds__(512, 1)
cheb_mma_kernel(const float* __restrict__ zin, int T,
                const u32* __restrict__ Cw, const float* __restrict__ cb,
                float* __restrict__ out) {
    extern __shared__ char smraw[];
    __shared__ float Lsm[NPAD * NPAD], L2sm[NPAD * NPAD];
    __shared__ float sbias[64];

    const u32 sb0 = smem_u32(smraw);
    const u32 sbase = (sb0 + 1023) & ~1023u;
    char* sm = smraw + (sbase - sb0);
    float* Yf = (float*)(sm + CH_OFF_Y);

    const int tid = threadIdx.x;
    const int wid = tid >> 5, lane = tid & 31;

    for (int i = tid; i < 12288; i += 512) {
        int s = i / 6144;
        int rem = i - s * 6144;
        int dg = rem >> 5, c2 = rem & 31;
        u32 byte = dg * 128 + c2 * 4;
        *(u32*)(sm + CH_OFF_W + s * 24576 + (byte ^ ((byte >> 3) & 0x70))) = Cw[i];
    }
    for (int i = tid; i < NPAD * NPAD; i += 512) { Lsm[i] = g_L[i]; L2sm[i] = g_L2[i]; }
    if (tid < 64) sbias[tid] = cb[tid];
    __syncthreads();

    const int ntt = (T + 2) / 3;
    const int ntiles = ntt * BATCH;

    const int mg = wid & 3;
    const int og = wid >> 2;
    const u32 a_row_l = lane & 15;
    const u32 a_koff  = (lane & 16) ? 16u : 0u;
    const u32 b_row_l = lane & 7;
    const u32 b_koff  = (lane & 8) ? 16u : 0u;
    const u32 b_sreg  = (lane & 16) ? 24576u : 0u;
    const int trow = lane >> 2, tcol = (lane & 3) * 2;

    const u64 bias2 = pk2(sbias[2 * lane], sbias[2 * lane + 1]);

    const int mt   = wid / 5;
    const int mgp  = wid - mt * 5;
    const int nb   = mgp * 7;
    const int ncnt = (NNODE - nb < 7) ? (NNODE - nb) : 7;

    for (int tile = blockIdx.x; tile < ntiles; tile += gridDim.x) {
        const int b  = tile / ntt;
        const int t0 = (tile % ntt) * 3;
        const size_t bbase = ((size_t)b * T + t0) * NSTR;

        __syncthreads();

        for (int i4 = tid; i4 < 120 * 16; i4 += 512) {
            int r = i4 >> 4, c4 = (i4 & 15) << 2;
            float4 v = *(const float4*)(zin + (bbase + r) * 64 + c4);
            __nv_bfloat16 hx = __float2bfloat16(v.x), hy = __float2bfloat16(v.y);
            __nv_bfloat16 hz = __float2bfloat16(v.z), hw = __float2bfloat16(v.w);
            u32 byte = r * 128 + (c4 << 1);
            u32 sw = byte ^ ((byte >> 3) & 0x70);
            *(u64*)(sm + CH_OFF_A + sw) = pack4bf(hx, hy, hz, hw);
            __nv_bfloat16 lx = __float2bfloat16(v.x - __bfloat162float(hx));
            __nv_bfloat16 ly = __float2bfloat16(v.y - __bfloat162float(hy));
            __nv_bfloat16 lz = __float2bfloat16(v.z - __bfloat162float(hz));
            __nv_bfloat16 lw = __float2bfloat16(v.w - __bfloat162float(hw));
            *(u64*)(sm + CH_OFF_A + 16384 + sw) = pack4bf(lx, ly, lz, lw);
        }
        __syncthreads();

        float acc[2][6][4];
#pragma unroll
        for (int mi = 0; mi < 2; mi++)
#pragma unroll
            for (int ot = 0; ot < 6; ot++)
#pragma unroll
                for (int c = 0; c < 4; c++) acc[mi][ot][c] = 0.f;

#pragma unroll
        for (int kc = 0; kc < 4; kc++) {
            u32 ah[2][4], al[2][4];
#pragma unroll
            for (int mi = 0; mi < 2; mi++) {
                u32 rb = (u32)(mg * 32 + mi * 16) + a_row_l;
                u32 byte = rb * 128 + (u32)(kc * 32) + a_koff;
                u32 sw = byte ^ ((byte >> 3) & 0x70);
                ldsm_x4(ah[mi], sbase + CH_OFF_A + sw);
                ldsm_x4(al[mi], sbase + CH_OFF_A + 16384u + sw);
            }
#pragma unroll
            for (int ot = 0; ot < 6; ot++) {
                u32 bf[4];
                u32 nr = (u32)(og * 48 + 8 * ot) + b_row_l;
                u32 byte = nr * 128 + (u32)(kc * 32) + b_koff;
                ldsm_x4(bf, sbase + CH_OFF_W + b_sreg + (byte ^ ((byte >> 3) & 0x70)));
#pragma unroll
                for (int mi = 0; mi < 2; mi++) {
                    mma_bf16(acc[mi][ot], ah[mi], bf[0], bf[1]);
                    mma_bf16(acc[mi][ot], al[mi], bf[0], bf[1]);
                    mma_bf16(acc[mi][ot], ah[mi], bf[2], bf[3]);
                }
            }
        }

#pragma unroll
        for (int mi = 0; mi < 2; mi++)
#pragma unroll
            for (int rs = 0; rs < 2; rs++) {
                int r = mg * 32 + mi * 16 + trow + rs * 8;
                if (r < 120) {
                    float* yp = Yf + r * CH_YSTR + og * 48;
#pragma unroll
                    for (int ot = 0; ot < 6; ot++)
                        *(float2*)(yp + 8 * ot + tcol) =
                            make_float2(acc[mi][ot][rs * 2], acc[mi][ot][rs * 2 + 1]);
                }
            }
        __syncthreads();

        if (wid < 15 && t0 + mt < T) {
            u64 acc2[7];
#pragma unroll
            for (int j = 0; j < 7; j++)
                acc2[j] = (j < ncnt)
                    ? *(const u64*)(Yf + (mt * 40 + nb + j) * CH_YSTR + 2 * lane)
                    : 0ull;
            const float* yt = Yf + (mt * 40) * CH_YSTR + 2 * lane;
#pragma unroll 3
            for (int m4 = 0; m4 < NPAD; m4 += 4) {
                u64 y1[4], y2[4];
#pragma unroll
                for (int q = 0; q < 4; q++) {
                    y1[q] = *(const u64*)(yt + (m4 + q) * CH_YSTR + 64);
                    y2[q] = *(const u64*)(yt + (m4 + q) * CH_YSTR + 128);
                }
#pragma unroll
                for (int j = 0; j < 7; j++) {
                    if (j < ncnt) {
                        float4 lv  = *(const float4*)(&Lsm [(nb + j) * NPAD + m4]);
                        float4 l2v = *(const float4*)(&L2sm[(nb + j) * NPAD + m4]);
                        fma2(acc2[j], y1[0], dup2(lv.x));
                        fma2(acc2[j], y1[1], dup2(lv.y));
                        fma2(acc2[j], y1[2], dup2(lv.z));
                        fma2(acc2[j], y1[3], dup2(lv.w));
                        fma2(acc2[j], y2[0], dup2(l2v.x));
                        fma2(acc2[j], y2[1], dup2(l2v.y));
                        fma2(acc2[j], y2[2], dup2(l2v.z));
                        fma2(acc2[j], y2[3], dup2(l2v.w));
                    }
                }
            }
#pragma unroll
            for (int j = 0; j < 7; j++) {
                if (j < ncnt) {
                    float f0, f1, b0, b1;
                    unpk2(acc2[j], f0, f1);
                    unpk2(bias2, b0, b1);
                    float2 hv = make_float2(fmaxf(f0 + b0, 0.f), fmaxf(f1 + b1, 0.f));
                    *(float2*)(out + (bbase + mt * 40 + nb + j) * 64 + 2 * lane) = hv;
                }
            }
        }
    }
}

// ---------------- BN finalize ----------------
__global__ void finalize_bn_kernel(const double* __restrict__ sum, const double* __restrict__ sqs,
                                   const float* __restrict__ gamma, const float* __restrict__ beta,
                                   double cnt, float* __restrict__ scl, float* __restrict__ shf) {
    int nn = threadIdx.x;
    if (nn < NNODE) {
        double m = sum[nn] / cnt;
        double v = sqs[nn] / cnt - m * m;
        double inv = 1.0 / sqrt(v + 1e-5);
        double sc = (double)gamma[nn] * inv;
        scl[nn] = (float)sc;
        shf[nn] = (float)((double)beta[nn] - m * sc);
    }
}

// ---------------- fused BN+relu+time-mean (256 threads: 8 warps split T) ----------------
__global__ void __launch_bounds__(256)
timemean_kernel(const float* __restrict__ x, int T,
                const float* __restrict__ scl, const float* __restrict__ shf) {
    __shared__ double red[8][64];
    const int n = blockIdx.x, b = blockIdx.y;
    const int tid = threadIdx.x, w = tid >> 5, lane = tid & 31;
    const float sc = scl[n], sh = shf[n];
    const float* xp = x + ((size_t)b * T * NSTR + n) * 64 + 2 * lane;
    double s0 = 0.0, s1 = 0.0;
    for (int t = w; t < T; t += 8) {
        float2 v = *(const float2*)(xp + (size_t)t * NSTR * 64);
        s0 += (double)fmaxf(fmaf(v.x, sc, sh), 0.f);
        s1 += (double)fmaxf(fmaf(v.y, sc, sh), 0.f);
    }
    red[w][2 * lane]     = s0;
    red[w][2 * lane + 1] = s1;
    __syncthreads();
    if (tid < 64) {
        double s = 0.0;
#pragma unroll
        for (int i = 0; i < 8; i++) s += red[i][tid];
        g_M[(b * NNODE + n) * CH + tid] = (float)(s / (double)T);
    }
}

// ---------------- classifier ----------------
__global__ void __launch_bounds__(256)
fc_kernel(const float* __restrict__ w1, const float* __restrict__ b1,
          const float* __restrict__ w2, const float* __restrict__ b2,
          float* __restrict__ out) {
    __shared__ float ms[NNODE * CH];
    __shared__ float h1[256];
    const int b = blockIdx.x, tid = threadIdx.x;
    for (int i = tid; i < NNODE * CH; i += 256) ms[i] = g_M[b * NNODE * CH + i];
    __syncthreads();
    double acc = (double)b1[tid];
    for (int i = 0; i < NNODE * CH; i++) acc += (double)ms[i] * (double)w1[i * 256 + tid];
    h1[tid] = fmaxf((float)acc, 0.f);
    __syncthreads();
    if (tid < 10) {
        double a2 = (double)b2[tid];
        for (int i = 0; i < 256; i++) a2 += (double)h1[i] * (double)w2[i * 10 + tid];
        out[b * 10 + tid] = (float)a2;
    }
}

// ---------------- launch ----------------
extern "C" void kernel_launch(void* const* d_in, const int* in_sizes, int n_in,
                              void* d_out, int out_size) {
    const float* x        = (const float*)d_in[0];
    const int*   ei       = (const int*)d_in[1];
    const float* s1_tc1_w = (const float*)d_in[2];
    const float* s1_tc1_b = (const float*)d_in[3];
    const float* s1_cheb_w= (const float*)d_in[4];
    const float* s1_cheb_b= (const float*)d_in[5];
    const float* s1_tc2_w = (const float*)d_in[6];
    const float* s1_tc2_b = (const float*)d_in[7];
    const float* s1_bn_g  = (const float*)d_in[8];
    const float* s1_bn_b  = (const float*)d_in[9];
    const float* s2_tc1_w = (const float*)d_in[10];
    const float* s2_tc1_b = (const float*)d_in[11];
    const float* s2_cheb_w= (const float*)d_in[12];
    const float* s2_cheb_b= (const float*)d_in[13];
    const float* s2_tc2_w = (const float*)d_in[14];
    const float* s2_tc2_b = (const float*)d_in[15];
    const float* s2_bn_g  = (const float*)d_in[16];
    const float* s2_bn_b  = (const float*)d_in[17];
    const float* fc1_w    = (const float*)d_in[18];
    const float* fc1_b    = (const float*)d_in[19];
    const float* fc2_w    = (const float*)d_in[20];
    const float* fc2_b    = (const float*)d_in[21];

    float *bufA, *bufB, *scl1, *shf1, *scl2, *shf2;
    u32 *Bw1, *Bw2, *Bw3, *Cw1, *Cw2;
    double *sum1, *sqs1, *sum2, *sqs2;
    cudaGetSymbolAddress((void**)&bufA, g_bufA);
    cudaGetSymbolAddress((void**)&bufB, g_bufB);
    cudaGetSymbolAddress((void**)&Bw1, g_Bw1);
    cudaGetSymbolAddress((void**)&Bw2, g_Bw2);
    cudaGetSymbolAddress((void**)&Bw3, g_Bw3);
    cudaGetSymbolAddress((void**)&Cw1, g_Cw1);
    cudaGetSymbolAddress((void**)&Cw2, g_Cw2);
    cudaGetSymbolAddress((void**)&scl1, g_scl1);
    cudaGetSymbolAddress((void**)&shf1, g_shf1);
    cudaGetSymbolAddress((void**)&scl2, g_scl2);
    cudaGetSymbolAddress((void**)&shf2, g_shf2);
    cudaGetSymbolAddress((void**)&sum1, g_sum1);
    cudaGetSymbolAddress((void**)&sqs1, g_sqs1);
    cudaGetSymbolAddress((void**)&sum2, g_sum2);
    cudaGetSymbolAddress((void**)&sqs2, g_sqs2);

    cudaFuncSetAttribute(tconv_mma_kernel, cudaFuncAttributeMaxDynamicSharedMemorySize, TC_SMEM);
    cudaFuncSetAttribute(cheb_mma_kernel,  cudaFuncAttributeMaxDynamicSharedMemorySize, CH_DYN);

    const int ne = in_sizes[1] / 2;
    const int GRID = 148;

    // launch order: profiled launch (index 3) = first cheb_mma
    setup_kernel<<<1, 64>>>(ei, ne, s1_tc1_w);                                        // 0
    tconv3_kernel<<<GRID, dim3(64, 8)>>>(x, s1_tc1_b, bufA);                          // 1: T=510
    convert_cw_kernel<<<96, 256>>>(s1_cheb_w, Cw1, s2_cheb_w, Cw2);                   // 2
    cheb_mma_kernel<<<GRID, 512, CH_DYN>>>(bufA, 510, Cw1, s1_cheb_b, bufB);          // 3 (profiled)
    convert_w_kernel<<<144, 256>>>(s1_tc2_w, Bw1);                                    // 4
    tconv_mma_kernel<<<GRID, 512, TC_SMEM>>>(bufB, 510, Bw1, s1_tc2_b,
                                             nullptr, nullptr, 0, bufA,
                                             sum1, sqs1);                              // 5: T=508 + BN1 stats
    convert_w_kernel<<<144, 256>>>(s2_tc1_w, Bw2);                                    // 6
    finalize_bn_kernel<<<1, 64>>>(sum1, sqs1, s1_bn_g, s1_bn_b,
                                  (double)BATCH * 508.0 * 64.0, scl1, shf1);          // 7

    // ---- STConv 2 (BN1+relu fused into A-conversion) ----
    tconv_mma_kernel<<<GRID, 512, TC_SMEM>>>(bufA, 508, Bw2, s2_tc1_b,
                                             scl1, shf1, 1, bufB,
                                             nullptr, nullptr);                        // 8: T=506
    convert_w_kernel<<<144, 256>>>(s2_tc2_w, Bw3);                                    // 9
    cheb_mma_kernel<<<GRID, 512, CH_DYN>>>(bufB, 506, Cw2, s2_cheb_b, bufA);          // 10
    tconv_mma_kernel<<<GRID, 512, TC_SMEM>>>(bufA, 506, Bw3, s2_tc2_b,
                                             nullptr, nullptr, 0, bufB,
                                             sum2, sqs2);                              // 11: T=504 + BN2 stats
    finalize_bn_kernel<<<1, 64>>>(sum2, sqs2, s2_bn_g, s2_bn_b,
                                  (double)BATCH * 504.0 * 64.0, scl2, shf2);          // 12

    // ---- head ----
    timemean_kernel<<<dim3(NNODE, BATCH), 256>>>(bufB, 504, scl2, shf2);              // 13
    fc_kernel<<<BATCH, 256>>>(fc1_w, fc1_b, fc2_w, fc2_b, (float*)d_out);             // 14
}

// round 13
// speedup vs baseline: 1.2399x; 1.0259x over previous
#include <cuda_runtime.h>
#include <cuda_bf16.h>
#include <math.h>

#define BATCH 32
#define NNODE 33
#define NSTR  40
#define NPAD  36
#define CH    64
#define MAXENT 1100

typedef unsigned long long u64;
typedef unsigned int u32;
typedef unsigned short u16;

// ---------------- f32x2 helpers ----------------
__device__ __forceinline__ u64 pk2(float lo, float hi) {
    u64 r;
    asm("mov.b64 %0, {%1, %2};" : "=l"(r) : "r"(__float_as_uint(lo)), "r"(__float_as_uint(hi)));
    return r;
}
__device__ __forceinline__ u64 dup2(float v) { return pk2(v, v); }
__device__ __forceinline__ void unpk2(u64 v, float& lo, float& hi) {
    u32 a, b;
    asm("mov.b64 {%0, %1}, %2;" : "=r"(a), "=r"(b) : "l"(v));
    lo = __uint_as_float(a);
    hi = __uint_as_float(b);
}
__device__ __forceinline__ void fma2(u64& d, u64 a, u64 b) {
    asm("fma.rn.f32x2 %0, %1, %2, %0;" : "+l"(d) : "l"(a), "l"(b));
}

// ---------------- mma.sync / ldmatrix helpers ----------------
__device__ __forceinline__ u32 smem_u32(const void* p) {
    u32 a;
    asm("{ .reg .u64 t; cvta.to.shared.u64 t, %1; cvt.u32.u64 %0, t; }" : "=r"(a) : "l"(p));
    return a;
}
__device__ __forceinline__ void ldsm_x4(u32* r, u32 addr) {
    asm volatile("ldmatrix.sync.aligned.m8n8.x4.shared.b16 {%0,%1,%2,%3}, [%4];"
                 : "=r"(r[0]), "=r"(r[1]), "=r"(r[2]), "=r"(r[3]) : "r"(addr));
}
__device__ __forceinline__ void mma_bf16(float* c, const u32* a, u32 b0, u32 b1) {
    asm volatile("mma.sync.aligned.m16n8k16.row.col.f32.bf16.bf16.f32 "
                 "{%0,%1,%2,%3}, {%4,%5,%6,%7}, {%8,%9}, {%0,%1,%2,%3};"
                 : "+f"(c[0]), "+f"(c[1]), "+f"(c[2]), "+f"(c[3])
                 : "r"(a[0]), "r"(a[1]), "r"(a[2]), "r"(a[3]), "r"(b0), "r"(b1));
}
__device__ __forceinline__ u64 pack4bf(__nv_bfloat16 a, __nv_bfloat16 b,
                                       __nv_bfloat16 c, __nv_bfloat16 d) {
    u32 u0 = ((u32)__bfloat16_as_ushort(b) << 16) | (u32)__bfloat16_as_ushort(a);
    u32 u1 = ((u32)__bfloat16_as_ushort(d) << 16) | (u32)__bfloat16_as_ushort(c);
    return (u64)u0 | ((u64)u1 << 32);
}
__device__ __forceinline__ void bfsplit(float v, u16& h, u16& l) {
    __nv_bfloat16 hb = __float2bfloat16(v);
    h = __bfloat16_as_ushort(hb);
    l = __bfloat16_as_ushort(__float2bfloat16(v - __bfloat162float(hb)));
}

// ---------------- device scratch ----------------
#define BUF_ELEMS ((size_t)BATCH * 510 * NSTR * CH)
__device__ float g_bufA[BUF_ELEMS];
__device__ float g_bufB[BUF_ELEMS];
__device__ float g_w1a[3 * 3 * 3 * 64];
__device__ u32   g_Bw1[36864], g_Bw2[36864], g_Bw3[36864];
__device__ u32   g_Cw1[12288], g_Cw2[12288];
__device__ int   g_rowptr[NNODE + 1];
__device__ int   g_entm[MAXENT];
__device__ float g_entL[MAXENT];
__device__ float g_entL2[MAXENT];
__device__ float g_scl1[NNODE], g_shf1[NNODE];
__device__ float g_scl2[NNODE], g_shf2[NNODE];
__device__ double g_sum1[NNODE], g_sqs1[NNODE];
__device__ double g_sum2[NNODE], g_sqs2[NNODE];
__device__ float g_M[BATCH * NNODE * CH];

// ---------------- setup: BN acc zero + tconv3 reorder + L, L^2 -> union CSR ----------------
__global__ void setup_kernel(const int* __restrict__ ei, int ne, const float* __restrict__ w3) {
    __shared__ float sL[NPAD * NPAD];
    __shared__ float sL2[NPAD * NPAD];
    int i = threadIdx.x;
    if (i < NNODE) { g_sum1[i] = 0.0; g_sqs1[i] = 0.0; g_sum2[i] = 0.0; g_sqs2[i] = 0.0; }
    for (int j = i; j < 3 * 3 * 3 * 64; j += 64) {
        int o  = j & 63;
        int k  = (j >> 6) % 3;
        int ci = (j / 192) % 3;
        int g  = j / (192 * 3);
        g_w1a[j] = w3[((g * 64 + o) * 3 + ci) * 3 + k];
    }
    if (i == 0) {
        double deg[NNODE];
        for (int k = 0; k < NNODE; k++) deg[k] = 0.0;
        for (int e = 0; e < ne; e++) deg[ei[e]] += 1.0;
        double dinv[NNODE];
        for (int k = 0; k < NNODE; k++) dinv[k] = (deg[k] > 0.0) ? (1.0 / sqrt(deg[k])) : 0.0;
        for (int k = 0; k < NPAD * NPAD; k++) sL[k] = 0.0f;
        for (int e = 0; e < ne; e++) {
            int s = ei[e];
            int t = ei[ne + e];
            sL[t * NPAD + s] += (float)(-dinv[s] * dinv[t]);
        }
    }
    __syncthreads();
    for (int idx = i; idx < NPAD * NPAD; idx += 64) {
        int r = idx / NPAD, c = idx % NPAD;
        float s = 0.f;
        for (int m = 0; m < NPAD; m++) s = fmaf(sL[r * NPAD + m], sL[m * NPAD + c], s);
        sL2[idx] = s;
    }
    __syncthreads();
    if (i == 0) {
        int p = 0;
        g_rowptr[0] = 0;
        for (int n = 0; n < NNODE; n++) {
            for (int m = 0; m < NNODE; m++) {
                float a = sL[n * NPAD + m], b = sL2[n * NPAD + m];
                if (a != 0.f || b != 0.f) {
                    g_entm[p] = m;
                    g_entL[p] = a;
                    g_entL2[p] = b;
                    p++;
                }
            }
            g_rowptr[n + 1] = p;
        }
    }
}

// ---- tconv weights -> bf16 hi/lo regions ----
__global__ void convert_w_kernel(const float* __restrict__ w, u32* __restrict__ outw) {
    int i = blockIdx.x * blockDim.x + threadIdx.x;
    if (i >= 36864) return;
    int region = i >> 11;
    int rem    = i & 2047;
    int o      = rem >> 5;
    int c2     = rem & 31;
    int s  = region & 1;
    int gk = region >> 1;
    int g  = gk / 3, k = gk % 3;
    int ci0 = 2 * c2;
    float v0 = w[((g * 64 + o) * 64 + ci0) * 3 + k];
    float v1 = w[((g * 64 + o) * 64 + ci0 + 1) * 3 + k];
    u16 h0, l0, h1, l1;
    bfsplit(v0, h0, l0);
    bfsplit(v1, h1, l1);
    outw[i] = (s == 0) ? (((u32)h1 << 16) | (u32)h0) : (((u32)l1 << 16) | (u32)l0);
}

// ---- cheb weights -> flat Veff [s][dg=k*64+d][c-pair], Veff = [W0-W2, W1, 2*W2] ----
__device__ __forceinline__ float veff(const float* cw, int k, int c, int d) {
    if (k == 0) return cw[(0 * 64 + c) * 64 + d] - cw[(2 * 64 + c) * 64 + d];
    if (k == 1) return cw[(1 * 64 + c) * 64 + d];
    return 2.f * cw[(2 * 64 + c) * 64 + d];
}
__global__ void convert_cw_kernel(const float* __restrict__ cw1, u32* __restrict__ o1,
                                  const float* __restrict__ cw2, u32* __restrict__ o2) {
    int i = blockIdx.x * blockDim.x + threadIdx.x;
    if (i >= 24576) return;
    const float* cw = (i < 12288) ? cw1 : cw2;
    u32* op = (i < 12288) ? o1 : o2;
    int j = (i < 12288) ? i : (i - 12288);
    int s   = j / 6144;
    int rem = j - s * 6144;
    int dg  = rem >> 5, c2 = rem & 31;
    int k = dg >> 6, d = dg & 63, c0 = 2 * c2;
    float v0 = veff(cw, k, c0, d);
    float v1 = veff(cw, k, c0 + 1, d);
    u16 h0, l0, h1, l1;
    bfsplit(v0, h0, l0);
    bfsplit(v1, h1, l1);
    op[j] = (s == 0) ? (((u32)h1 << 16) | (u32)h0) : (((u32)l1 << 16) | (u32)l0);
}

// ---------------- SIMT gated tconv CI=3 (first layer) ----------------
__global__ void __launch_bounds__(512)
tconv3_kernel(const float* __restrict__ xin,
              const float* __restrict__ bias,
              float* __restrict__ out) {
    constexpr int CI = 3, CT = 128, TO = 16, ST = CT + 4, HP = TO / 2;
    constexpr int Tin = 512, Tout = 510;
    __shared__ float ws[3 * CI * 3 * 64];
    __shared__ float xs[CI * ST];

    const int tid = threadIdx.y * 64 + threadIdx.x;
    const int ntch = (Tout + CT - 1) / CT;
    const int ntiles = ntch * NNODE * BATCH;

    for (int i = tid; i < 3 * CI * 3 * 64; i += 512) ws[i] = g_w1a[i];

    const int o  = threadIdx.x;
    const int tb = threadIdx.y * TO;
    const float bP = bias[o], bQ = bias[64 + o], bR = bias[128 + o];

    for (int tile = blockIdx.x; tile < ntiles; tile += gridDim.x) {
        const int tch = tile % ntch;
        const int rem = tile / ntch;
        const int n   = rem % NNODE;
        const int b   = rem / NNODE;
        const int t0  = tch * CT;

        __syncthreads();
        for (int i = tid; i < (CT + 2) * CI; i += 512) {
            int tt = i / CI, ci = i % CI;
            int t = t0 + tt;
            float v = 0.f;
            if (t < Tin) v = xin[(((size_t)b * Tin + t) * NNODE + n) * CI + ci];
            xs[ci * ST + tt] = v;
        }
        __syncthreads();

        u64 accP[3][HP];
#pragma unroll
        for (int g = 0; g < 3; g++)
#pragma unroll
            for (int p = 0; p < HP; p++) accP[g][p] = 0ull;

#pragma unroll
        for (int ci = 0; ci < CI; ci++) {
            const float* xp = &xs[ci * ST + tb];
            u64 ep[HP + 1];
#pragma unroll
            for (int p = 0; p <= HP; p++) ep[p] = *reinterpret_cast<const u64*>(xp + 2 * p);
            float xl[HP + 1], xh[HP + 1];
#pragma unroll
            for (int p = 0; p <= HP; p++) unpk2(ep[p], xl[p], xh[p]);
            u64 op[HP];
#pragma unroll
            for (int p = 0; p < HP; p++) op[p] = pk2(xh[p], xl[p + 1]);

#pragma unroll
            for (int g = 0; g < 3; g++) {
#pragma unroll
                for (int k = 0; k < 3; k++) {
                    u64 wd = dup2(ws[((g * CI + ci) * 3 + k) * 64 + o]);
                    const u64* xq = (k == 0) ? ep : (k == 1) ? op : (ep + 1);
#pragma unroll
                    for (int p = 0; p < HP; p++) fma2(accP[g][p], xq[p], wd);
                }
            }
        }

#pragma unroll
        for (int p = 0; p < HP; p++) {
            float P0, P1, Q0, Q1, R0, R1;
            unpk2(accP[0][p], P0, P1);
            unpk2(accP[1][p], Q0, Q1);
            unpk2(accP[2][p], R0, R1);
#pragma unroll
            for (int half = 0; half < 2; half++) {
                int t = t0 + tb + 2 * p + half;
                if (t < Tout) {
                    float P = (half ? P1 : P0) + bP;
                    float Q = (half ? Q1 : Q0) + bQ;
                    float R = (half ? R1 : R0) + bR;
                    float sg = 1.f / (1.f + __expf(-Q));
                    float h = fmaxf(fmaf(P, sg, R), 0.f);
                    out[(((size_t)b * Tout + t) * NSTR + n) * CH + o] = h;
                }
            }
        }
    }
}

// ---------------- mma.sync gated tconv CI=64 (512 threads, fused BN stats) ----------------
#define ROWS_A 208
#define A_SPLIT_B (ROWS_A * 128)
#define B_BYTES   (18 * 8192)
#define OFF_B     1024
#define OFF_A     (OFF_B + B_BYTES)
#define TC_SMEM   (OFF_A + 2 * A_SPLIT_B + 1024)

__global__ void __launch_bounds__(512, 1)
tconv_mma_kernel(const float* __restrict__ xin, int Tin,
                 const u32* __restrict__ Bw,
                 const float* __restrict__ bias,
                 const float* __restrict__ scl, const float* __restrict__ shf, int mode,
                 float* __restrict__ out,
                 double* bnsum, double* bnsqs) {
    extern __shared__ char smraw[];
    __shared__ float sbias[192];
    __shared__ float sbn1[NNODE], sbn2[NNODE];

    const u32 sb0 = smem_u32(smraw);
    const u32 sbase = (sb0 + 1023) & ~1023u;
    char* sm = smraw + (sbase - sb0);

    const int tid = threadIdx.x;
    const int wid = tid >> 5, lane = tid & 31;
    const int Tout = Tin - 2;
    const int RowsIn = Tin * NSTR, RowsOut = Tout * NSTR;
    const int ntb = (RowsOut + 127) / 128;
    const int ntiles = ntb * BATCH;
    const int dostats = (bnsum != nullptr);

    for (int i = tid; i < 36864; i += 512) {
        int r = i >> 11, rem = i & 2047, row = rem >> 5, c2 = rem & 31;
        u32 byte = row * 128 + c2 * 4;
        *(u32*)(sm + OFF_B + r * 8192 + (byte ^ ((byte >> 3) & 0x70))) = Bw[i];
    }
    if (tid < 192) sbias[tid] = bias[tid];
    if (tid < NNODE) { sbn1[tid] = 0.f; sbn2[tid] = 0.f; }
    __syncthreads();

    const int warp_m = wid & 7;
    const int o0 = (wid >> 3) * 32;

    const u32 a_row_l = lane & 15;
    const u32 a_koff  = (lane & 16) ? 16u : 0u;
    const u32 b_row_l = lane & 7;
    const u32 b_koff  = (lane & 8) ? 16u : 0u;
    const u32 b_sreg  = (lane & 16) ? 8192u : 0u;

    const int trow = lane >> 2;
    const int tcol = (lane & 3) * 2;

    for (int tile = blockIdx.x; tile < ntiles; tile += gridDim.x) {
        const int bidx = tile / ntb, tl = tile % ntb;
        const int local0 = tl * 128;
        const float* xb = xin + (size_t)bidx * RowsIn * 64;

        __syncthreads();

        for (int i4 = tid; i4 < ROWS_A * 16; i4 += 512) {
            int r = i4 >> 4, c4 = (i4 & 15) << 2;
            int il = local0 + r;
            float4 v = make_float4(0.f, 0.f, 0.f, 0.f);
            if (il < RowsIn) {
                int n = il % NSTR;
                if (n < NNODE) {
                    v = *(const float4*)(xb + (size_t)il * 64 + c4);
                    if (mode) {
                        float sc = scl[n], sh = shf[n];
                        v.x = fmaxf(fmaf(v.x, sc, sh), 0.f);
                        v.y = fmaxf(fmaf(v.y, sc, sh), 0.f);
                        v.z = fmaxf(fmaf(v.z, sc, sh), 0.f);
                        v.w = fmaxf(fmaf(v.w, sc, sh), 0.f);
                    }
                }
            }
            __nv_bfloat16 hx = __float2bfloat16(v.x), hy = __float2bfloat16(v.y);
            __nv_bfloat16 hz = __float2bfloat16(v.z), hw = __float2bfloat16(v.w);
            u32 byte = r * 128 + (c4 << 1);
            u32 sw = byte ^ ((byte >> 3) & 0x70);
            *(u64*)(sm + OFF_A + sw) = pack4bf(hx, hy, hz, hw);
            __nv_bfloat16 lx = __float2bfloat16(v.x - __bfloat162float(hx));
            __nv_bfloat16 ly = __float2bfloat16(v.y - __bfloat162float(hy));
            __nv_bfloat16 lz = __float2bfloat16(v.z - __bfloat162float(hz));
            __nv_bfloat16 lw = __float2bfloat16(v.w - __bfloat162float(hw));
            *(u64*)(sm + OFF_A + A_SPLIT_B + sw) = pack4bf(lx, ly, lz, lw);
        }
        __syncthreads();

        float acc[3][4][4];
#pragma unroll
        for (int g = 0; g < 3; g++)
#pragma unroll
            for (int ot = 0; ot < 4; ot++)
#pragma unroll
                for (int c = 0; c < 4; c++) acc[g][ot][c] = 0.f;

#pragma unroll
        for (int tap = 0; tap < 3; tap++) {
#pragma unroll
            for (int kc = 0; kc < 4; kc++) {
                u32 ah[4], al[4];
                {
                    u32 rb = (u32)(tap * 40 + warp_m * 16) + a_row_l;
                    u32 byte = rb * 128 + (u32)(kc * 32) + a_koff;
                    u32 sw = byte ^ ((byte >> 3) & 0x70);
                    ldsm_x4(ah, sbase + OFF_A + sw);
                    ldsm_x4(al, sbase + OFF_A + A_SPLIT_B + sw);
                }
#pragma unroll
                for (int g = 0; g < 3; g++) {
                    u32 breg = sbase + OFF_B + (u32)((g * 3 + tap) * 2) * 8192 + b_sreg;
                    u32 bf[4][4];
#pragma unroll
                    for (int ot = 0; ot < 4; ot++) {
                        u32 byte = (u32)(o0 + 8 * ot + (int)b_row_l) * 128 + (u32)(kc * 32) + b_koff;
                        ldsm_x4(bf[ot], breg + (byte ^ ((byte >> 3) & 0x70)));
                    }
#pragma unroll
                    for (int ot = 0; ot < 4; ot++)
                        mma_bf16(acc[g][ot], ah, bf[ot][0], bf[ot][1]);
#pragma unroll
                    for (int ot = 0; ot < 4; ot++)
                        mma_bf16(acc[g][ot], al, bf[ot][0], bf[ot][1]);
#pragma unroll
                    for (int ot = 0; ot < 4; ot++)
                        mma_bf16(acc[g][ot], ah, bf[ot][2], bf[ot][3]);
                }
            }
        }

#pragma unroll
        for (int rs = 0; rs < 2; rs++) {
            int row = warp_m * 16 + trow + rs * 8;
            int ol = local0 + row;
            const bool valid = (ol < RowsOut);
            const int n = ol % NSTR;

            float hv[8];
            float s1 = 0.f, s2 = 0.f;
#pragma unroll
            for (int ot = 0; ot < 4; ot++) {
                int o = o0 + 8 * ot + tcol;
#pragma unroll
                for (int e = 0; e < 2; e++) {
                    float P = acc[0][ot][rs * 2 + e] + sbias[o + e];
                    float Q = acc[1][ot][rs * 2 + e] + sbias[64 + o + e];
                    float R = acc[2][ot][rs * 2 + e] + sbias[128 + o + e];
                    float sg = 1.f / (1.f + __expf(-Q));
                    float h = fmaxf(fmaf(P, sg, R), 0.f);
                    hv[2 * ot + e] = h;
                    s1 += h;
                    s2 += h * h;
                }
            }

            if (dostats) {
                if (!valid || n >= NNODE) { s1 = 0.f; s2 = 0.f; }
                s1 += __shfl_xor_sync(0xffffffffu, s1, 1);
                s1 += __shfl_xor_sync(0xffffffffu, s1, 2);
                s2 += __shfl_xor_sync(0xffffffffu, s2, 1);
                s2 += __shfl_xor_sync(0xffffffffu, s2, 2);
                if ((lane & 3) == 0 && valid && n < NNODE) {
                    atomicAdd(&sbn1[n], s1);
                    atomicAdd(&sbn2[n], s2);
                }
            }

            if (valid) {
                float* op = out + ((size_t)bidx * RowsOut + ol) * 64 + o0;
#pragma unroll
                for (int ot = 0; ot < 4; ot++)
                    *(float2*)(op + 8 * ot + tcol) = make_float2(hv[2 * ot], hv[2 * ot + 1]);
            }
        }
    }

    if (dostats) {
        __syncthreads();
        if (tid < NNODE) {
            atomicAdd(&bnsum[tid], (double)sbn1[tid]);
            atomicAdd(&bnsqs[tid], (double)sbn2[tid]);
        }
    }
}

// ---------------- cheb v5: GEMM-first + SPARSE CSR fp32 L-mixing ----------------
#define CH_OFF_W  0
#define CH_OFF_A  49152
#define CH_OFF_Y  81920
#define CH_YSTR   196
#define CH_DYN    (81920 + 120 * 196 * 4 + 2048)

__global__ void __launch_bounds__(512, 1)
cheb_mma_kernel(const float* __restrict__ zin, int T,
                const u32* __restrict__ Cw, const float* __restrict__ cb,
                float* __restrict__ out) {
    extern __shared__ char smraw[];
    __shared__ int   srp[NNODE + 1];
    __shared__ int   sem[MAXENT];
    __shared__ float seL[MAXENT], seL2[MAXENT];
    __shared__ float sbias[64];

    const u32 sb0 = smem_u32(smraw);
    const u32 sbase = (sb0 + 1023) & ~1023u;
    char* sm = smraw + (sbase - sb0);
    float* Yf = (float*)(sm + CH_OFF_Y);

    const int tid = threadIdx.x;
    const int wid = tid >> 5, lane = tid & 31;

    for (int i = tid; i < 12288; i += 512) {
        int s = i / 6144;
        int rem = i - s * 6144;
        int dg = rem >> 5, c2 = rem & 31;
        u32 byte = dg * 128 + c2 * 4;
        *(u32*)(sm + CH_OFF_W + s * 24576 + (byte ^ ((byte >> 3) & 0x70))) = Cw[i];
    }
    if (tid <= NNODE) srp[tid] = g_rowptr[tid];
    for (int i = tid; i < MAXENT; i += 512) {
        sem[i] = g_entm[i];
        seL[i] = g_entL[i];
        seL2[i] = g_entL2[i];
    }
    if (tid < 64) sbias[tid] = cb[tid];
    __syncthreads();

    const int ntt = (T + 2) / 3;
    const int ntiles = ntt * BATCH;

    const int mg = wid & 3;          // m32 group (GEMM)
    const int og = wid >> 2;         // n48 group (GEMM)
    const u32 a_row_l = lane & 15;
    const u32 a_koff  = (lane & 16) ? 16u : 0u;
    const u32 b_row_l = lane & 7;
    const u32 b_koff  = (lane & 8) ? 16u : 0u;
    const u32 b_sreg  = (lane & 16) ? 24576u : 0u;
    const int trow = lane >> 2, tcol = (lane & 3) * 2;

    const u64 bias2 = pk2(sbias[2 * lane], sbias[2 * lane + 1]);

    for (int tile = blockIdx.x; tile < ntiles; tile += gridDim.x) {
        const int b  = tile / ntt;
        const int t0 = (tile % ntt) * 3;
        const size_t bbase = ((size_t)b * T + t0) * NSTR;

        __syncthreads();

        // ---- fill: Z bf16 hi/lo ----
        for (int i4 = tid; i4 < 120 * 16; i4 += 512) {
            int r = i4 >> 4, c4 = (i4 & 15) << 2;
            float4 v = *(const float4*)(zin + (bbase + r) * 64 + c4);
            __nv_bfloat16 hx = __float2bfloat16(v.x), hy = __float2bfloat16(v.y);
            __nv_bfloat16 hz = __float2bfloat16(v.z), hw = __float2bfloat16(v.w);
            u32 byte = r * 128 + (c4 << 1);
            u32 sw = byte ^ ((byte >> 3) & 0x70);
            *(u64*)(sm + CH_OFF_A + sw) = pack4bf(hx, hy, hz, hw);
            __nv_bfloat16 lx = __float2bfloat16(v.x - __bfloat162float(hx));
            __nv_bfloat16 ly = __float2bfloat16(v.y - __bfloat162float(hy));
            __nv_bfloat16 lz = __float2bfloat16(v.z - __bfloat162float(hz));
            __nv_bfloat16 lw = __float2bfloat16(v.w - __bfloat162float(hw));
            *(u64*)(sm + CH_OFF_A + 16384 + sw) = pack4bf(lx, ly, lz, lw);
        }
        __syncthreads();

        // ---- GEMM: Y[128x192] = Z[128x64] * Veff[64x192] ----
        float acc[2][6][4];
#pragma unroll
        for (int mi = 0; mi < 2; mi++)
#pragma unroll
            for (int ot = 0; ot < 6; ot++)
#pragma unroll
                for (int c = 0; c < 4; c++) acc[mi][ot][c] = 0.f;

#pragma unroll
        for (int kc = 0; kc < 4; kc++) {
            u32 ah[2][4], al[2][4];
#pragma unroll
            for (int mi = 0; mi < 2; mi++) {
                u32 rb = (u32)(mg * 32 + mi * 16) + a_row_l;
                u32 byte = rb * 128 + (u32)(kc * 32) + a_koff;
                u32 sw = byte ^ ((byte >> 3) & 0x70);
                ldsm_x4(ah[mi], sbase + CH_OFF_A + sw);
                ldsm_x4(al[mi], sbase + CH_OFF_A + 16384u + sw);
            }
#pragma unroll
            for (int ot = 0; ot < 6; ot++) {
                u32 bf[4];
                u32 nr = (u32)(og * 48 + 8 * ot) + b_row_l;
                u32 byte = nr * 128 + (u32)(kc * 32) + b_koff;
                ldsm_x4(bf, sbase + CH_OFF_W + b_sreg + (byte ^ ((byte >> 3) & 0x70)));
#pragma unroll
                for (int mi = 0; mi < 2; mi++) {
                    mma_bf16(acc[mi][ot], ah[mi], bf[0], bf[1]);
                    mma_bf16(acc[mi][ot], al[mi], bf[0], bf[1]);
                    mma_bf16(acc[mi][ot], ah[mi], bf[2], bf[3]);
                }
            }
        }

        // ---- Y store (fp32, stride 196) ----
#pragma unroll
        for (int mi = 0; mi < 2; mi++)
#pragma unroll
            for (int rs = 0; rs < 2; rs++) {
                int r = mg * 32 + mi * 16 + trow + rs * 8;
                if (r < 120) {
                    float* yp = Yf + r * CH_YSTR + og * 48;
#pragma unroll
                    for (int ot = 0; ot < 6; ot++)
                        *(float2*)(yp + 8 * ot + tcol) =
                            make_float2(acc[mi][ot][rs * 2], acc[mi][ot][rs * 2 + 1]);
                }
            }
        __syncthreads();

        // ---- sparse mixing: out = relu(Y0 + L*Y1 + L2*Y2 + bias) ----
        for (int p = wid; p < 3 * NNODE; p += 16) {
            const int t = p / NNODE, n = p - t * NNODE;
            if (t0 + t >= T) continue;
            const float* yt = Yf + (t * 40) * CH_YSTR + 2 * lane;
            u64 acc2 = *(const u64*)(Yf + (t * 40 + n) * CH_YSTR + 2 * lane);  // Y0[n]
            const int e0 = srp[n], e1 = srp[n + 1];
            for (int e = e0; e < e1; e++) {
                int m = sem[e];
                u64 y1 = *(const u64*)(yt + m * CH_YSTR + 64);
                u64 y2 = *(const u64*)(yt + m * CH_YSTR + 128);
                fma2(acc2, y1, dup2(seL[e]));
                fma2(acc2, y2, dup2(seL2[e]));
            }
            float f0, f1, b0, b1;
            unpk2(acc2, f0, f1);
            unpk2(bias2, b0, b1);
            *(float2*)(out + (bbase + t * 40 + n) * 64 + 2 * lane) =
                make_float2(fmaxf(f0 + b0, 0.f), fmaxf(f1 + b1, 0.f));
        }
    }
}

// ---------------- BN finalize ----------------
__global__ void finalize_bn_kernel(const double* __restrict__ sum, const double* __restrict__ sqs,
                                   const float* __restrict__ gamma, const float* __restrict__ beta,
                                   double cnt, float* __restrict__ scl, float* __restrict__ shf) {
    int nn = threadIdx.x;
    if (nn < NNODE) {
        double m = sum[nn] / cnt;
        double v = sqs[nn] / cnt - m * m;
        double inv = 1.0 / sqrt(v + 1e-5);
        double sc = (double)gamma[nn] * inv;
        scl[nn] = (float)sc;
        shf[nn] = (float)((double)beta[nn] - m * sc);
    }
}

// ---------------- fused BN+relu+time-mean (256 threads) ----------------
__global__ void __launch_bounds__(256)
timemean_kernel(const float* __restrict__ x, int T,
                const float* __restrict__ scl, const float* __restrict__ shf) {
    __shared__ double red[8][64];
    const int n = blockIdx.x, b = blockIdx.y;
    const int tid = threadIdx.x, w = tid >> 5, lane = tid & 31;
    const float sc = scl[n], sh = shf[n];
    const float* xp = x + ((size_t)b * T * NSTR + n) * 64 + 2 * lane;
    double s0 = 0.0, s1 = 0.0;
    for (int t = w; t < T; t += 8) {
        float2 v = *(const float2*)(xp + (size_t)t * NSTR * 64);
        s0 += (double)fmaxf(fmaf(v.x, sc, sh), 0.f);
        s1 += (double)fmaxf(fmaf(v.y, sc, sh), 0.f);
    }
    red[w][2 * lane]     = s0;
    red[w][2 * lane + 1] = s1;
    __syncthreads();
    if (tid < 64) {
        double s = 0.0;
#pragma unroll
        for (int i = 0; i < 8; i++) s += red[i][tid];
        g_M[(b * NNODE + n) * CH + tid] = (float)(s / (double)T);
    }
}

// ---------------- classifier ----------------
__global__ void __launch_bounds__(256)
fc_kernel(const float* __restrict__ w1, const float* __restrict__ b1,
          const float* __restrict__ w2, const float* __restrict__ b2,
          float* __restrict__ out) {
    __shared__ float ms[NNODE * CH];
    __shared__ float h1[256];
    const int b = blockIdx.x, tid = threadIdx.x;
    for (int i = tid; i < NNODE * CH; i += 256) ms[i] = g_M[b * NNODE * CH + i];
    __syncthreads();
    double acc = (double)b1[tid];
    for (int i = 0; i < NNODE * CH; i++) acc += (double)ms[i] * (double)w1[i * 256 + tid];
    h1[tid] = fmaxf((float)acc, 0.f);
    __syncthreads();
    if (tid < 10) {
        double a2 = (double)b2[tid];
        for (int i = 0; i < 256; i++) a2 += (double)h1[i] * (double)w2[i * 10 + tid];
        out[b * 10 + tid] = (float)a2;
    }
}

// ---------------- launch ----------------
extern "C" void kernel_launch(void* const* d_in, const int* in_sizes, int n_in,
                              void* d_out, int out_size) {
    const float* x        = (const float*)d_in[0];
    const int*   ei       = (const int*)d_in[1];
    const float* s1_tc1_w = (const float*)d_in[2];
    const float* s1_tc1_b = (const float*)d_in[3];
    const float* s1_cheb_w= (const float*)d_in[4];
    const float* s1_cheb_b= (const float*)d_in[5];
    const float* s1_tc2_w = (const float*)d_in[6];
    const float* s1_tc2_b = (const float*)d_in[7];
    const float* s1_bn_g  = (const float*)d_in[8];
    const float* s1_bn_b  = (const float*)d_in[9];
    const float* s2_tc1_w = (const float*)d_in[10];
    const float* s2_tc1_b = (const float*)d_in[11];
    const float* s2_cheb_w= (const float*)d_in[12];
    const float* s2_cheb_b= (const float*)d_in[13];
    const float* s2_tc2_w = (const float*)d_in[14];
    const float* s2_tc2_b = (const float*)d_in[15];
    const float* s2_bn_g  = (const float*)d_in[16];
    const float* s2_bn_b  = (const float*)d_in[17];
    const float* fc1_w    = (const float*)d_in[18];
    const float* fc1_b    = (const float*)d_in[19];
    const float* fc2_w    = (const float*)d_in[20];
    const float* fc2_b    = (const float*)d_in[21];

    float *bufA, *bufB, *scl1, *shf1, *scl2, *shf2;
    u32 *Bw1, *Bw2, *Bw3, *Cw1, *Cw2;
    double *sum1, *sqs1, *sum2, *sqs2;
    cudaGetSymbolAddress((void**)&bufA, g_bufA);
    cudaGetSymbolAddress((void**)&bufB, g_bufB);
    cudaGetSymbolAddress((void**)&Bw1, g_Bw1);
    cudaGetSymbolAddress((void**)&Bw2, g_Bw2);
    cudaGetSymbolAddress((void**)&Bw3, g_Bw3);
    cudaGetSymbolAddress((void**)&Cw1, g_Cw1);
    cudaGetSymbolAddress((void**)&Cw2, g_Cw2);
    cudaGetSymbolAddress((void**)&scl1, g_scl1);
    cudaGetSymbolAddress((void**)&shf1, g_shf1);
    cudaGetSymbolAddress((void**)&scl2, g_scl2);
    cudaGetSymbolAddress((void**)&shf2, g_shf2);
    cudaGetSymbolAddress((void**)&sum1, g_sum1);
    cudaGetSymbolAddress((void**)&sqs1, g_sqs1);
    cudaGetSymbolAddress((void**)&sum2, g_sum2);
    cudaGetSymbolAddress((void**)&sqs2, g_sqs2);

    cudaFuncSetAttribute(tconv_mma_kernel, cudaFuncAttributeMaxDynamicSharedMemorySize, TC_SMEM);
    cudaFuncSetAttribute(cheb_mma_kernel,  cudaFuncAttributeMaxDynamicSharedMemorySize, CH_DYN);

    const int ne = in_sizes[1] / 2;
    const int GRID = 148;

    // launch order: profiled launch (index 3) = first cheb_mma
    setup_kernel<<<1, 64>>>(ei, ne, s1_tc1_w);                                        // 0
    tconv3_kernel<<<GRID, dim3(64, 8)>>>(x, s1_tc1_b, bufA);                          // 1: T=510
    convert_cw_kernel<<<96, 256>>>(s1_cheb_w, Cw1, s2_cheb_w, Cw2);                   // 2
    cheb_mma_kernel<<<GRID, 512, CH_DYN>>>(bufA, 510, Cw1, s1_cheb_b, bufB);          // 3 (profiled)
    convert_w_kernel<<<144, 256>>>(s1_tc2_w, Bw1);                                    // 4
    tconv_mma_kernel<<<GRID, 512, TC_SMEM>>>(bufB, 510, Bw1, s1_tc2_b,
                                             nullptr, nullptr, 0, bufA,
                                             sum1, sqs1);                              // 5: T=508 + BN1 stats
    convert_w_kernel<<<144, 256>>>(s2_tc1_w, Bw2);                                    // 6
    finalize_bn_kernel<<<1, 64>>>(sum1, sqs1, s1_bn_g, s1_bn_b,
                                  (double)BATCH * 508.0 * 64.0, scl1, shf1);          // 7

    // ---- STConv 2 (BN1+relu fused into A-conversion) ----
    tconv_mma_kernel<<<GRID, 512, TC_SMEM>>>(bufA, 508, Bw2, s2_tc1_b,
                                             scl1, shf1, 1, bufB,
                                             nullptr, nullptr);                        // 8: T=506
    convert_w_kernel<<<144, 256>>>(s2_tc2_w, Bw3);                                    // 9
    cheb_mma_kernel<<<GRID, 512, CH_DYN>>>(bufB, 506, Cw2, s2_cheb_b, bufA);          // 10
    tconv_mma_kernel<<<GRID, 512, TC_SMEM>>>(bufA, 506, Bw3, s2_tc2_b,
                                             nullptr, nullptr, 0, bufB,
                                             sum2, sqs2);                              // 11: T=504 + BN2 stats
    finalize_bn_kernel<<<1, 64>>>(sum2, sqs2, s2_bn_g, s2_bn_b,
                                  (double)BATCH * 504.0 * 64.0, scl2, shf2);          // 12

    // ---- head ----
    timemean_kernel<<<dim3(NNODE, BATCH), 256>>>(bufB, 504, scl2, shf2);              // 13
    fc_kernel<<<BATCH, 256>>>(fc1_w, fc1_b, fc2_w, fc2_b, (float*)d_out);             // 14
}